// round 1
// baseline (speedup 1.0000x reference)
#include <cuda_runtime.h>
#include <cuda_bf16.h>

// Problem constants (fixed by setup_inputs)
#define BS     4
#define NQ     4000
#define EMBED  256
#define NH     8
#define NL     4
#define NP     4
#define HD     32
#define NV     13294   // 100*100 + 50*50 + 25*25 + 13*13

__constant__ int c_H[NL]     = {100, 50, 25, 13};
__constant__ int c_W[NL]     = {100, 50, 25, 13};
__constant__ int c_start[NL] = {0, 10000, 12500, 13125};

// Scratch (device globals: allocation-free per harness rules)
__device__ float g_v[BS * NV * EMBED];     // projected value  [b, pos, h*HD+d]
__device__ float g_off[BS * NQ * 256];     // offsets          [b,q, h,l,p,c]
__device__ float g_attn[BS * NQ * 128];    // attn logits      [b,q, h, l*NP+p]
__device__ float g_samp[BS * NQ * EMBED];  // sampled output   [b,q, h*HD+d]

// ---------------------------------------------------------------------------
// Tiled fp32 GEMM: C[M,N] = A[M,256] @ B[256,N] + bias[N]
// BM=64, BN=64, BK=16, 256 threads, 4x4 micro-tile per thread.
// ---------------------------------------------------------------------------
#define BM 64
#define BN 64
#define BK 16

__global__ __launch_bounds__(256) void gemm_k256(
    const float* __restrict__ A, const float* __restrict__ B,
    const float* __restrict__ bias, float* __restrict__ C,
    int M, int N)
{
    __shared__ float As[BK][BM + 4];   // +4 pad: 16B-aligned rows, kills STS conflicts
    __shared__ float Bs[BK][BN];

    const int m0 = blockIdx.x * BM;
    const int n0 = blockIdx.y * BN;
    const int t  = threadIdx.x;
    const int tx = t & 15;
    const int ty = t >> 4;

    float acc[4][4] = {};

    for (int k0 = 0; k0 < 256; k0 += BK) {
        // Load A tile (64 rows x 16 k), store transposed As[k][m]
        #pragma unroll
        for (int i = 0; i < 4; i++) {
            int idx = t + i * 256;          // 0..1023
            int r = idx >> 4, k = idx & 15;
            int row = m0 + r; if (row >= M) row = M - 1;
            As[k][r] = A[row * 256 + k0 + k];
        }
        // Load B tile (16 k x 64 n)
        #pragma unroll
        for (int i = 0; i < 4; i++) {
            int idx = t + i * 256;
            int k = idx >> 6, n = idx & 63;
            Bs[k][n] = B[(k0 + k) * N + n0 + n];
        }
        __syncthreads();

        #pragma unroll
        for (int k = 0; k < BK; k++) {
            float4 a  = *(const float4*)&As[k][ty * 4];
            float4 bv = *(const float4*)&Bs[k][tx * 4];
            float av[4] = {a.x, a.y, a.z, a.w};
            float bb[4] = {bv.x, bv.y, bv.z, bv.w};
            #pragma unroll
            for (int i = 0; i < 4; i++)
                #pragma unroll
                for (int j = 0; j < 4; j++)
                    acc[i][j] += av[i] * bb[j];
        }
        __syncthreads();
    }

    #pragma unroll
    for (int i = 0; i < 4; i++) {
        int row = m0 + ty * 4 + i;
        if (row < M) {
            #pragma unroll
            for (int j = 0; j < 4; j++) {
                int col = n0 + tx * 4 + j;
                C[row * N + col] = acc[i][j] + bias[col];
            }
        }
    }
}

// ---------------------------------------------------------------------------
// Fused softmax + bilinear sampling.
// One warp per (b, q, h); lane = hd channel (HD == 32 == warpSize).
// ---------------------------------------------------------------------------
__global__ __launch_bounds__(256) void ms_deform_sample(
    const float* __restrict__ refp)   // [bs, nq, NL, 2]
{
    const int warp = (blockIdx.x * blockDim.x + threadIdx.x) >> 5;
    const int lane = threadIdx.x & 31;
    if (warp >= BS * NQ * NH) return;

    const int h  = warp % NH;
    const int bq = warp / NH;      // b * NQ + q
    const int b  = bq / NQ;

    // --- per-point scalars held on lanes 0..15 (lp = l*NP + p) ---
    float logit = -1e30f, xv = 0.f, yv = 0.f;
    if (lane < 16) {
        logit = g_attn[bq * 128 + h * 16 + lane];
        float ox = g_off[bq * 256 + h * 32 + lane * 2 + 0];
        float oy = g_off[bq * 256 + h * 32 + lane * 2 + 1];
        int l = lane >> 2;
        float rx = refp[(bq * NL + l) * 2 + 0];
        float ry = refp[(bq * NL + l) * 2 + 1];
        // pixel coords: (ref + off/norm) * dim - 0.5 == ref*dim + off - 0.5
        xv = rx * (float)c_W[l] + ox - 0.5f;
        yv = ry * (float)c_H[l] + oy - 0.5f;
    }

    // --- softmax over 16 (full-warp butterfly; lanes>=16 neutral) ---
    float m = logit;
    #pragma unroll
    for (int o = 16; o >= 1; o >>= 1) m = fmaxf(m, __shfl_xor_sync(0xFFFFFFFFu, m, o));
    float e = (lane < 16) ? __expf(logit - m) : 0.f;
    float s = e;
    #pragma unroll
    for (int o = 16; o >= 1; o >>= 1) s += __shfl_xor_sync(0xFFFFFFFFu, s, o);
    const float wgt = e / s;

    const float* vbase = g_v + (size_t)b * NV * EMBED + h * HD;
    float acc = 0.f;

    #pragma unroll
    for (int p = 0; p < 16; p++) {
        const float x  = __shfl_sync(0xFFFFFFFFu, xv,  p);
        const float y  = __shfl_sync(0xFFFFFFFFu, yv,  p);
        const float aw = __shfl_sync(0xFFFFFFFFu, wgt, p);
        const int l  = p >> 2;
        const int W  = c_W[l];
        const int H  = c_H[l];
        const int st = c_start[l];

        const float x0f = floorf(x), y0f = floorf(y);
        const int   x0  = (int)x0f,  y0  = (int)y0f;
        const float fx = x - x0f, fy = y - y0f;
        const float w00 = (1.f - fx) * (1.f - fy) * aw;
        const float w10 = fx * (1.f - fy) * aw;
        const float w01 = (1.f - fx) * fy * aw;
        const float w11 = fx * fy * aw;

        const bool vx0 = (x0 >= 0)     && (x0 < W);
        const bool vx1 = (x0 + 1 >= 0) && (x0 + 1 < W);
        const bool vy0 = (y0 >= 0)     && (y0 < H);
        const bool vy1 = (y0 + 1 >= 0) && (y0 + 1 < H);

        const float* pb = vbase + (size_t)st * EMBED;
        if (vy0) {
            int ro = y0 * W * EMBED;
            if (vx0) acc += w00 * pb[ro + x0 * EMBED + lane];
            if (vx1) acc += w10 * pb[ro + (x0 + 1) * EMBED + lane];
        }
        if (vy1) {
            int ro = (y0 + 1) * W * EMBED;
            if (vx0) acc += w01 * pb[ro + x0 * EMBED + lane];
            if (vx1) acc += w11 * pb[ro + (x0 + 1) * EMBED + lane];
        }
    }

    g_samp[bq * EMBED + h * HD + lane] = acc;
}

// ---------------------------------------------------------------------------
extern "C" void kernel_launch(void* const* d_in, const int* in_sizes, int n_in,
                              void* d_out, int out_size)
{
    const float* query  = (const float*)d_in[0];
    const float* value  = (const float*)d_in[1];
    const float* refp   = (const float*)d_in[2];
    // d_in[3] = spatial_shapes (int32) — values are compile-time constants here
    const float* W_off  = (const float*)d_in[4];
    const float* b_off  = (const float*)d_in[5];
    const float* W_attn = (const float*)d_in[6];
    const float* b_attn = (const float*)d_in[7];
    const float* W_val  = (const float*)d_in[8];
    const float* b_val  = (const float*)d_in[9];
    const float* W_out  = (const float*)d_in[10];
    const float* b_out  = (const float*)d_in[11];
    float* out = (float*)d_out;

    float* gv;    cudaGetSymbolAddress((void**)&gv,    g_v);
    float* goff;  cudaGetSymbolAddress((void**)&goff,  g_off);
    float* gattn; cudaGetSymbolAddress((void**)&gattn, g_attn);
    float* gsamp; cudaGetSymbolAddress((void**)&gsamp, g_samp);

    const int Mv = BS * NV;      // 53176
    const int Mq = BS * NQ;      // 16000

    // 1) value projection
    {
        dim3 grid((Mv + BM - 1) / BM, EMBED / BN);
        gemm_k256<<<grid, 256>>>(value, W_val, b_val, gv, Mv, EMBED);
    }
    // 2) offsets projection
    {
        dim3 grid(Mq / BM, 256 / BN);
        gemm_k256<<<grid, 256>>>(query, W_off, b_off, goff, Mq, 256);
    }
    // 3) attention logits projection
    {
        dim3 grid(Mq / BM, 128 / BN);
        gemm_k256<<<grid, 256>>>(query, W_attn, b_attn, gattn, Mq, 128);
    }
    // 4) fused softmax + bilinear sampling
    {
        int warps = BS * NQ * NH;               // 128000
        int blocks = (warps * 32 + 255) / 256;  // 16000
        ms_deform_sample<<<blocks, 256>>>(refp);
    }
    // 5) output projection
    {
        dim3 grid(Mq / BM, EMBED / BN);
        gemm_k256<<<grid, 256>>>(gsamp, W_out, b_out, out, Mq, EMBED);
    }
}

// round 3
// speedup vs baseline: 2.6884x; 2.6884x over previous
#include <cuda_runtime.h>
#include <cuda_bf16.h>
#include <cstdint>
#include <cstddef>

// Problem constants (fixed by setup_inputs)
#define BS     4
#define NQ     4000
#define EMBED  256
#define NH     8
#define NL     4
#define NP     4
#define HD     32
#define NV     13294   // 100*100 + 50*50 + 25*25 + 13*13

__constant__ int c_H[NL]     = {100, 50, 25, 13};
__constant__ int c_W[NL]     = {100, 50, 25, 13};
__constant__ int c_start[NL] = {0, 10000, 12500, 13125};

// Scratch (device globals: allocation-free per harness rules)
__device__ float g_v[BS * NV * EMBED];     // projected value  [b, pos, h*HD+d]
__device__ float g_off[BS * NQ * 256];     // offsets          [b,q, h,l,p,c]
__device__ float g_attn[BS * NQ * 128];    // attn logits      [b,q, h, l*NP+p]
__device__ float g_samp[BS * NQ * EMBED];  // sampled output   [b,q, h*HD+d]

__device__ __forceinline__ uint32_t tf32r(float f) {
    uint32_t r;
    asm("cvt.rna.tf32.f32 %0, %1;" : "=r"(r) : "f"(f));
    return r;
}

// ---------------------------------------------------------------------------
// tf32 mma.sync GEMM: C[M,N] = A[M,256] @ B[256,N] + bias[N]
// Block tile 128x64, K-chunk 32. 256 threads = 8 warps (4 m x 2 n),
// warp tile 32x32 = 2x4 m16n8k8 fragments.
// SMEM strides of 36 make fragment reads bank-conflict-free.
// ---------------------------------------------------------------------------
#define BM 128
#define BN 64
#define BK 32
#define ASTRIDE 36
#define BSTRIDE 36

__global__ __launch_bounds__(256) void gemm_mma(
    const float* __restrict__ A, const float* __restrict__ Bw,
    const float* __restrict__ bias, float* __restrict__ C,
    int M, int N)
{
    __shared__ uint32_t As[BM * ASTRIDE];   // [m][k] tf32 bits, 18432 B
    __shared__ uint32_t Bs[BN * BSTRIDE];   // [n][k] tf32 bits,  9216 B

    const int t      = threadIdx.x;
    const int lane   = t & 31;
    const int wid    = t >> 5;
    const int warp_m = wid & 3;          // 0..3
    const int warp_n = wid >> 2;         // 0..1
    const int m0     = blockIdx.x * BM;
    const int n0     = blockIdx.y * BN;

    const int lr = lane >> 2;            // 0..7
    const int lc = lane & 3;             // 0..3

    float acc[2][4][4];
    #pragma unroll
    for (int i = 0; i < 2; i++)
        #pragma unroll
        for (int j = 0; j < 4; j++)
            #pragma unroll
            for (int r = 0; r < 4; r++) acc[i][j][r] = 0.f;

    for (int k0 = 0; k0 < 256; k0 += BK) {
        // --- stage A tile: 128 rows x 32 k ---
        #pragma unroll
        for (int i = 0; i < 4; ++i) {
            int idx = t + i * 256;       // 0..1023 float4 slots
            int r = idx >> 3, f = idx & 7;
            int rg = m0 + r; if (rg >= M) rg = M - 1;
            float4 v = *(const float4*)(A + (size_t)rg * 256 + k0 + f * 4);
            uint32_t* dst = As + r * ASTRIDE + f * 4;
            dst[0] = tf32r(v.x); dst[1] = tf32r(v.y);
            dst[2] = tf32r(v.z); dst[3] = tf32r(v.w);
        }
        // --- stage B tile transposed: Bs[n][k] = Bw[k0+k][n0+n] ---
        #pragma unroll
        for (int i = 0; i < 2; ++i) {
            int idx = t + i * 256;       // 0..511 float4 slots
            int k = idx >> 4, nf = idx & 15;
            float4 v = *(const float4*)(Bw + (size_t)(k0 + k) * N + n0 + nf * 4);
            Bs[(nf * 4 + 0) * BSTRIDE + k] = tf32r(v.x);
            Bs[(nf * 4 + 1) * BSTRIDE + k] = tf32r(v.y);
            Bs[(nf * 4 + 2) * BSTRIDE + k] = tf32r(v.z);
            Bs[(nf * 4 + 3) * BSTRIDE + k] = tf32r(v.w);
        }
        __syncthreads();

        #pragma unroll
        for (int ks = 0; ks < BK; ks += 8) {
            uint32_t a[2][4], b[4][2];
            #pragma unroll
            for (int mt = 0; mt < 2; ++mt) {
                const int base = warp_m * 32 + mt * 16;
                a[mt][0] = As[(base + lr)     * ASTRIDE + ks + lc];
                a[mt][1] = As[(base + lr + 8) * ASTRIDE + ks + lc];
                a[mt][2] = As[(base + lr)     * ASTRIDE + ks + lc + 4];
                a[mt][3] = As[(base + lr + 8) * ASTRIDE + ks + lc + 4];
            }
            #pragma unroll
            for (int nt = 0; nt < 4; ++nt) {
                const int n = warp_n * 32 + nt * 8 + lr;
                b[nt][0] = Bs[n * BSTRIDE + ks + lc];
                b[nt][1] = Bs[n * BSTRIDE + ks + lc + 4];
            }
            #pragma unroll
            for (int mt = 0; mt < 2; ++mt)
                #pragma unroll
                for (int nt = 0; nt < 4; ++nt) {
                    asm volatile(
                        "mma.sync.aligned.m16n8k8.row.col.f32.tf32.tf32.f32 "
                        "{%0,%1,%2,%3}, {%4,%5,%6,%7}, {%8,%9}, {%0,%1,%2,%3};"
                        : "+f"(acc[mt][nt][0]), "+f"(acc[mt][nt][1]),
                          "+f"(acc[mt][nt][2]), "+f"(acc[mt][nt][3])
                        : "r"(a[mt][0]), "r"(a[mt][1]), "r"(a[mt][2]), "r"(a[mt][3]),
                          "r"(b[nt][0]), "r"(b[nt][1]));
                }
        }
        __syncthreads();
    }

    // --- epilogue: add bias, store ---
    #pragma unroll
    for (int mt = 0; mt < 2; ++mt) {
        const int row = m0 + warp_m * 32 + mt * 16 + lr;
        #pragma unroll
        for (int nt = 0; nt < 4; ++nt) {
            const int col = n0 + warp_n * 32 + nt * 8 + lc * 2;
            const float b0 = bias[col], b1 = bias[col + 1];
            if (row < M) {
                float2 o0 = make_float2(acc[mt][nt][0] + b0, acc[mt][nt][1] + b1);
                *(float2*)(C + (size_t)row * N + col) = o0;
            }
            if (row + 8 < M) {
                float2 o1 = make_float2(acc[mt][nt][2] + b0, acc[mt][nt][3] + b1);
                *(float2*)(C + (size_t)(row + 8) * N + col) = o1;
            }
        }
    }
}

// ---------------------------------------------------------------------------
// Fused softmax + bilinear sampling.
// One warp per (b, q, h); lane = hd channel (HD == 32 == warpSize).
// ---------------------------------------------------------------------------
__global__ __launch_bounds__(256) void ms_deform_sample(
    const float* __restrict__ refp)   // [bs, nq, NL, 2]
{
    const int warp = (blockIdx.x * blockDim.x + threadIdx.x) >> 5;
    const int lane = threadIdx.x & 31;
    if (warp >= BS * NQ * NH) return;

    const int h  = warp % NH;
    const int bq = warp / NH;
    const int b  = bq / NQ;

    float logit = -1e30f, xv = 0.f, yv = 0.f;
    if (lane < 16) {
        logit = g_attn[bq * 128 + h * 16 + lane];
        float ox = g_off[bq * 256 + h * 32 + lane * 2 + 0];
        float oy = g_off[bq * 256 + h * 32 + lane * 2 + 1];
        int l = lane >> 2;
        float rx = refp[(bq * NL + l) * 2 + 0];
        float ry = refp[(bq * NL + l) * 2 + 1];
        xv = rx * (float)c_W[l] + ox - 0.5f;
        yv = ry * (float)c_H[l] + oy - 0.5f;
    }

    float m = logit;
    #pragma unroll
    for (int o = 16; o >= 1; o >>= 1) m = fmaxf(m, __shfl_xor_sync(0xFFFFFFFFu, m, o));
    float e = (lane < 16) ? __expf(logit - m) : 0.f;
    float s = e;
    #pragma unroll
    for (int o = 16; o >= 1; o >>= 1) s += __shfl_xor_sync(0xFFFFFFFFu, s, o);
    const float wgt = e / s;

    const float* vbase = g_v + (size_t)b * NV * EMBED + h * HD;
    float acc = 0.f;

    #pragma unroll
    for (int p = 0; p < 16; p++) {
        const float x  = __shfl_sync(0xFFFFFFFFu, xv,  p);
        const float y  = __shfl_sync(0xFFFFFFFFu, yv,  p);
        const float aw = __shfl_sync(0xFFFFFFFFu, wgt, p);
        const int l  = p >> 2;
        const int W  = c_W[l];
        const int H  = c_H[l];
        const int st = c_start[l];

        const float x0f = floorf(x), y0f = floorf(y);
        const int   x0  = (int)x0f,  y0  = (int)y0f;
        const float fx = x - x0f, fy = y - y0f;
        const float w00 = (1.f - fx) * (1.f - fy) * aw;
        const float w10 = fx * (1.f - fy) * aw;
        const float w01 = (1.f - fx) * fy * aw;
        const float w11 = fx * fy * aw;

        const bool vx0 = (x0 >= 0)     && (x0 < W);
        const bool vx1 = (x0 + 1 >= 0) && (x0 + 1 < W);
        const bool vy0 = (y0 >= 0)     && (y0 < H);
        const bool vy1 = (y0 + 1 >= 0) && (y0 + 1 < H);

        const float* pb = vbase + (size_t)st * EMBED;
        if (vy0) {
            int ro = y0 * W * EMBED;
            if (vx0) acc += w00 * pb[ro + x0 * EMBED + lane];
            if (vx1) acc += w10 * pb[ro + (x0 + 1) * EMBED + lane];
        }
        if (vy1) {
            int ro = (y0 + 1) * W * EMBED;
            if (vx0) acc += w01 * pb[ro + x0 * EMBED + lane];
            if (vx1) acc += w11 * pb[ro + (x0 + 1) * EMBED + lane];
        }
    }

    g_samp[bq * EMBED + h * HD + lane] = acc;
}

// ---------------------------------------------------------------------------
extern "C" void kernel_launch(void* const* d_in, const int* in_sizes, int n_in,
                              void* d_out, int out_size)
{
    const float* query  = (const float*)d_in[0];
    const float* value  = (const float*)d_in[1];
    const float* refp   = (const float*)d_in[2];
    const float* W_off  = (const float*)d_in[4];
    const float* b_off  = (const float*)d_in[5];
    const float* W_attn = (const float*)d_in[6];
    const float* b_attn = (const float*)d_in[7];
    const float* W_val  = (const float*)d_in[8];
    const float* b_val  = (const float*)d_in[9];
    const float* W_out  = (const float*)d_in[10];
    const float* b_out  = (const float*)d_in[11];
    float* out = (float*)d_out;

    float* gv;    cudaGetSymbolAddress((void**)&gv,    g_v);
    float* goff;  cudaGetSymbolAddress((void**)&goff,  g_off);
    float* gattn; cudaGetSymbolAddress((void**)&gattn, g_attn);
    float* gsamp; cudaGetSymbolAddress((void**)&gsamp, g_samp);

    const int Mv = BS * NV;      // 53176
    const int Mq = BS * NQ;      // 16000

    // 1) value projection
    gemm_mma<<<dim3((Mv + BM - 1) / BM, EMBED / BN), 256>>>(value, W_val, b_val, gv, Mv, EMBED);
    // 2) offsets projection
    gemm_mma<<<dim3(Mq / BM, 256 / BN), 256>>>(query, W_off, b_off, goff, Mq, 256);
    // 3) attention logits projection
    gemm_mma<<<dim3(Mq / BM, 128 / BN), 256>>>(query, W_attn, b_attn, gattn, Mq, 128);
    // 4) fused softmax + bilinear sampling
    {
        int warps = BS * NQ * NH;               // 128000
        int blocks = (warps * 32 + 255) / 256;  // 16000
        ms_deform_sample<<<blocks, 256>>>(refp);
    }
    // 5) output projection
    gemm_mma<<<dim3(Mq / BM, EMBED / BN), 256>>>(gsamp, W_out, b_out, out, Mq, EMBED);
}

// round 4
// speedup vs baseline: 3.1607x; 1.1757x over previous
#include <cuda_runtime.h>
#include <cuda_bf16.h>
#include <cstdint>
#include <cstddef>

// Problem constants (fixed by setup_inputs)
#define BS     4
#define NQ     4000
#define EMBED  256
#define NH     8
#define NL     4
#define NP     4
#define HD     32
#define NV     13294   // 100*100 + 50*50 + 25*25 + 13*13

__constant__ int c_H[NL]     = {100, 50, 25, 13};
__constant__ int c_W[NL]     = {100, 50, 25, 13};
__constant__ int c_start[NL] = {0, 10000, 12500, 13125};

// Scratch (device globals: allocation-free per harness rules)
__device__ float g_v[BS * NV * EMBED];     // projected value  [b, pos, h*HD+d]
__device__ float g_off[BS * NQ * 256];     // offsets          [b,q, h,l,p,c]
__device__ float g_attn[BS * NQ * 128];    // attn logits      [b,q, h, l*NP+p]
__device__ float g_samp[BS * NQ * EMBED];  // sampled output   [b,q, h*HD+d]

__device__ __forceinline__ uint32_t tf32r(float f) {
    uint32_t r;
    asm("cvt.rna.tf32.f32 %0, %1;" : "=r"(r) : "f"(f));
    return r;
}

// ---------------------------------------------------------------------------
// tf32 mma.sync GEMM: C[M,N] = A[M,256] @ B[256,N] + bias[N]
// Block tile 128x64, K-chunk 32. 256 threads = 8 warps (4 m x 2 n),
// warp tile 32x32 = 2x4 m16n8k8 fragments. Register-prefetch mainloop.
// ---------------------------------------------------------------------------
#define BM 128
#define BN 64
#define BK 32
#define ASTRIDE 36
#define BSTRIDE 36

__global__ __launch_bounds__(256) void gemm_mma(
    const float* __restrict__ A, const float* __restrict__ Bw,
    const float* __restrict__ bias, float* __restrict__ C,
    int M, int N)
{
    __shared__ uint32_t As[BM * ASTRIDE];   // [m][k] tf32 bits
    __shared__ uint32_t Bs[BN * BSTRIDE];   // [n][k] tf32 bits

    const int t      = threadIdx.x;
    const int lane   = t & 31;
    const int wid    = t >> 5;
    const int warp_m = wid & 3;
    const int warp_n = wid >> 2;
    const int m0     = blockIdx.x * BM;
    const int n0     = blockIdx.y * BN;

    const int lr = lane >> 2;            // 0..7
    const int lc = lane & 3;             // 0..3

    // A staging indices: idx = t + i*256 -> row r=idx>>3, float4 slot f=idx&7
    int arow[4];
    #pragma unroll
    for (int i = 0; i < 4; ++i) {
        int idx = t + i * 256;
        int rg = m0 + (idx >> 3);
        if (rg >= M) rg = M - 1;
        arow[i] = rg;
    }

    float4 a_reg[4], b_reg[2];
    #pragma unroll
    for (int i = 0; i < 4; ++i)
        a_reg[i] = *(const float4*)(A + (size_t)arow[i] * 256 + ((t + i * 256) & 7) * 4);
    #pragma unroll
    for (int i = 0; i < 2; ++i) {
        int idx = t + i * 256;
        b_reg[i] = *(const float4*)(Bw + (size_t)(idx >> 4) * N + n0 + (idx & 15) * 4);
    }

    float acc[2][4][4];
    #pragma unroll
    for (int i = 0; i < 2; i++)
        #pragma unroll
        for (int j = 0; j < 4; j++)
            #pragma unroll
            for (int r = 0; r < 4; r++) acc[i][j][r] = 0.f;

    for (int c = 0; c < 8; ++c) {
        // --- commit staged regs to smem ---
        #pragma unroll
        for (int i = 0; i < 4; ++i) {
            int idx = t + i * 256;
            uint32_t* dst = As + (idx >> 3) * ASTRIDE + (idx & 7) * 4;
            dst[0] = tf32r(a_reg[i].x); dst[1] = tf32r(a_reg[i].y);
            dst[2] = tf32r(a_reg[i].z); dst[3] = tf32r(a_reg[i].w);
        }
        #pragma unroll
        for (int i = 0; i < 2; ++i) {
            int idx = t + i * 256;
            int k = idx >> 4, nf = idx & 15;
            Bs[(nf * 4 + 0) * BSTRIDE + k] = tf32r(b_reg[i].x);
            Bs[(nf * 4 + 1) * BSTRIDE + k] = tf32r(b_reg[i].y);
            Bs[(nf * 4 + 2) * BSTRIDE + k] = tf32r(b_reg[i].z);
            Bs[(nf * 4 + 3) * BSTRIDE + k] = tf32r(b_reg[i].w);
        }
        __syncthreads();

        // --- prefetch next chunk while computing this one ---
        if (c < 7) {
            const int k0 = (c + 1) * BK;
            #pragma unroll
            for (int i = 0; i < 4; ++i)
                a_reg[i] = *(const float4*)(A + (size_t)arow[i] * 256 + k0 + ((t + i * 256) & 7) * 4);
            #pragma unroll
            for (int i = 0; i < 2; ++i) {
                int idx = t + i * 256;
                b_reg[i] = *(const float4*)(Bw + (size_t)(k0 + (idx >> 4)) * N + n0 + (idx & 15) * 4);
            }
        }

        #pragma unroll
        for (int ks = 0; ks < BK; ks += 8) {
            uint32_t a[2][4], b[4][2];
            #pragma unroll
            for (int mt = 0; mt < 2; ++mt) {
                const int base = warp_m * 32 + mt * 16;
                a[mt][0] = As[(base + lr)     * ASTRIDE + ks + lc];
                a[mt][1] = As[(base + lr + 8) * ASTRIDE + ks + lc];
                a[mt][2] = As[(base + lr)     * ASTRIDE + ks + lc + 4];
                a[mt][3] = As[(base + lr + 8) * ASTRIDE + ks + lc + 4];
            }
            #pragma unroll
            for (int nt = 0; nt < 4; ++nt) {
                const int n = warp_n * 32 + nt * 8 + lr;
                b[nt][0] = Bs[n * BSTRIDE + ks + lc];
                b[nt][1] = Bs[n * BSTRIDE + ks + lc + 4];
            }
            #pragma unroll
            for (int mt = 0; mt < 2; ++mt)
                #pragma unroll
                for (int nt = 0; nt < 4; ++nt) {
                    asm volatile(
                        "mma.sync.aligned.m16n8k8.row.col.f32.tf32.tf32.f32 "
                        "{%0,%1,%2,%3}, {%4,%5,%6,%7}, {%8,%9}, {%0,%1,%2,%3};"
                        : "+f"(acc[mt][nt][0]), "+f"(acc[mt][nt][1]),
                          "+f"(acc[mt][nt][2]), "+f"(acc[mt][nt][3])
                        : "r"(a[mt][0]), "r"(a[mt][1]), "r"(a[mt][2]), "r"(a[mt][3]),
                          "r"(b[nt][0]), "r"(b[nt][1]));
                }
        }
        __syncthreads();
    }

    // --- epilogue: add bias, store ---
    #pragma unroll
    for (int mt = 0; mt < 2; ++mt) {
        const int row = m0 + warp_m * 32 + mt * 16 + lr;
        #pragma unroll
        for (int nt = 0; nt < 4; ++nt) {
            const int col = n0 + warp_n * 32 + nt * 8 + lc * 2;
            const float b0 = bias[col], b1 = bias[col + 1];
            if (row < M) {
                float2 o0 = make_float2(acc[mt][nt][0] + b0, acc[mt][nt][1] + b1);
                *(float2*)(C + (size_t)row * N + col) = o0;
            }
            if (row + 8 < M) {
                float2 o1 = make_float2(acc[mt][nt][2] + b0, acc[mt][nt][3] + b1);
                *(float2*)(C + (size_t)(row + 8) * N + col) = o1;
            }
        }
    }
}

// ---------------------------------------------------------------------------
// Fused softmax + bilinear sampling, vectorized.
// One warp per (b, q, h). Lane group g = lane>>3 handles point p = level*4+g;
// channel quad c4 = lane&7 covers channels [4*c4, 4*c4+4) via float4.
// All 4 points of an iteration share one level -> W/H/start warp-uniform.
// ---------------------------------------------------------------------------
__global__ __launch_bounds__(256) void ms_deform_sample(
    const float* __restrict__ refp)   // [bs, nq, NL, 2]
{
    const int warp = (blockIdx.x * blockDim.x + threadIdx.x) >> 5;
    const int lane = threadIdx.x & 31;
    if (warp >= BS * NQ * NH) return;

    const int h  = warp % NH;
    const int bq = warp / NH;
    const int b  = bq / NQ;

    // --- per-point scalars on lanes 0..15 (index = l*NP + p) ---
    float logit = -1e30f, xv = 0.f, yv = 0.f;
    if (lane < 16) {
        logit = g_attn[bq * 128 + h * 16 + lane];
        float ox = g_off[bq * 256 + h * 32 + lane * 2 + 0];
        float oy = g_off[bq * 256 + h * 32 + lane * 2 + 1];
        int l = lane >> 2;
        float rx = refp[(bq * NL + l) * 2 + 0];
        float ry = refp[(bq * NL + l) * 2 + 1];
        xv = rx * (float)c_W[l] + ox - 0.5f;
        yv = ry * (float)c_H[l] + oy - 0.5f;
    }

    // --- softmax over the 16 points ---
    float m = logit;
    #pragma unroll
    for (int o = 16; o >= 1; o >>= 1) m = fmaxf(m, __shfl_xor_sync(0xFFFFFFFFu, m, o));
    float e = (lane < 16) ? __expf(logit - m) : 0.f;
    float s = e;
    #pragma unroll
    for (int o = 16; o >= 1; o >>= 1) s += __shfl_xor_sync(0xFFFFFFFFu, s, o);
    const float wgt = e / s;

    const int g  = lane >> 3;     // point group 0..3
    const int c4 = lane & 7;      // channel quad 0..7
    const float* vb = g_v + (size_t)b * NV * EMBED + h * HD + c4 * 4;

    float4 acc = make_float4(0.f, 0.f, 0.f, 0.f);

    #pragma unroll
    for (int l = 0; l < NL; ++l) {
        const int p = l * 4 + g;                         // this lane's point
        const float x  = __shfl_sync(0xFFFFFFFFu, xv,  p);
        const float y  = __shfl_sync(0xFFFFFFFFu, yv,  p);
        const float aw = __shfl_sync(0xFFFFFFFFu, wgt, p);
        const int W  = c_W[l];                           // warp-uniform
        const int H  = c_H[l];
        const int st = c_start[l];

        const float x0f = floorf(x), y0f = floorf(y);
        const int   x0  = (int)x0f,  y0  = (int)y0f;
        const int   x1  = x0 + 1,    y1  = y0 + 1;
        const float fx = x - x0f, fy = y - y0f;

        const float vx0 = (x0 >= 0 && x0 < W) ? 1.f : 0.f;
        const float vx1 = (x1 >= 0 && x1 < W) ? 1.f : 0.f;
        const float vy0 = (y0 >= 0 && y0 < H) ? 1.f : 0.f;
        const float vy1 = (y1 >= 0 && y1 < H) ? 1.f : 0.f;

        const int x0c = min(max(x0, 0), W - 1);
        const int x1c = min(max(x1, 0), W - 1);
        const int y0c = min(max(y0, 0), H - 1);
        const int y1c = min(max(y1, 0), H - 1);

        const float w00 = (1.f - fx) * (1.f - fy) * aw * vx0 * vy0;
        const float w10 = fx * (1.f - fy) * aw * vx1 * vy0;
        const float w01 = (1.f - fx) * fy * aw * vx0 * vy1;
        const float w11 = fx * fy * aw * vx1 * vy1;

        const float* pb = vb + (size_t)st * EMBED;
        const float4 v00 = *(const float4*)(pb + (size_t)(y0c * W + x0c) * EMBED);
        const float4 v10 = *(const float4*)(pb + (size_t)(y0c * W + x1c) * EMBED);
        const float4 v01 = *(const float4*)(pb + (size_t)(y1c * W + x0c) * EMBED);
        const float4 v11 = *(const float4*)(pb + (size_t)(y1c * W + x1c) * EMBED);

        acc.x += w00 * v00.x + w10 * v10.x + w01 * v01.x + w11 * v11.x;
        acc.y += w00 * v00.y + w10 * v10.y + w01 * v01.y + w11 * v11.y;
        acc.z += w00 * v00.z + w10 * v10.z + w01 * v01.z + w11 * v11.z;
        acc.w += w00 * v00.w + w10 * v10.w + w01 * v01.w + w11 * v11.w;
    }

    // --- reduce across the 4 point groups (lanes differing in bits 3,4) ---
    #pragma unroll
    for (int o = 8; o <= 16; o <<= 1) {
        acc.x += __shfl_xor_sync(0xFFFFFFFFu, acc.x, o);
        acc.y += __shfl_xor_sync(0xFFFFFFFFu, acc.y, o);
        acc.z += __shfl_xor_sync(0xFFFFFFFFu, acc.z, o);
        acc.w += __shfl_xor_sync(0xFFFFFFFFu, acc.w, o);
    }
    if (lane < 8)
        *(float4*)(g_samp + (size_t)bq * EMBED + h * HD + lane * 4) = acc;
}

// ---------------------------------------------------------------------------
extern "C" void kernel_launch(void* const* d_in, const int* in_sizes, int n_in,
                              void* d_out, int out_size)
{
    const float* query  = (const float*)d_in[0];
    const float* value  = (const float*)d_in[1];
    const float* refp   = (const float*)d_in[2];
    const float* W_off  = (const float*)d_in[4];
    const float* b_off  = (const float*)d_in[5];
    const float* W_attn = (const float*)d_in[6];
    const float* b_attn = (const float*)d_in[7];
    const float* W_val  = (const float*)d_in[8];
    const float* b_val  = (const float*)d_in[9];
    const float* W_out  = (const float*)d_in[10];
    const float* b_out  = (const float*)d_in[11];
    float* out = (float*)d_out;

    float* gv;    cudaGetSymbolAddress((void**)&gv,    g_v);
    float* goff;  cudaGetSymbolAddress((void**)&goff,  g_off);
    float* gattn; cudaGetSymbolAddress((void**)&gattn, g_attn);
    float* gsamp; cudaGetSymbolAddress((void**)&gsamp, g_samp);

    const int Mv = BS * NV;      // 53176
    const int Mq = BS * NQ;      // 16000

    // 1) value projection
    gemm_mma<<<dim3((Mv + BM - 1) / BM, EMBED / BN), 256>>>(value, W_val, b_val, gv, Mv, EMBED);
    // 2) offsets projection
    gemm_mma<<<dim3(Mq / BM, 256 / BN), 256>>>(query, W_off, b_off, goff, Mq, 256);
    // 3) attention logits projection
    gemm_mma<<<dim3(Mq / BM, 128 / BN), 256>>>(query, W_attn, b_attn, gattn, Mq, 128);
    // 4) fused softmax + bilinear sampling
    {
        int warps = BS * NQ * NH;               // 128000
        int blocks = (warps * 32 + 255) / 256;  // 16000
        ms_deform_sample<<<blocks, 256>>>(refp);
    }
    // 5) output projection
    gemm_mma<<<dim3(Mq / BM, EMBED / BN), 256>>>(gsamp, W_out, b_out, out, Mq, EMBED);
}

// round 5
// speedup vs baseline: 3.9020x; 1.2345x over previous
#include <cuda_runtime.h>
#include <cuda_bf16.h>
#include <cstdint>
#include <cstddef>

// Problem constants (fixed by setup_inputs)
#define BS     4
#define NQ     4000
#define EMBED  256
#define NH     8
#define NL     4
#define NP     4
#define HD     32
#define NV     13294   // 100*100 + 50*50 + 25*25 + 13*13

__constant__ int c_H[NL]     = {100, 50, 25, 13};
__constant__ int c_W[NL]     = {100, 50, 25, 13};
__constant__ int c_start[NL] = {0, 10000, 12500, 13125};

// Scratch (device globals: allocation-free per harness rules)
__device__ __align__(16) float g_v[BS * NV * EMBED];      // projected value
__device__ __align__(16) float g_qproj[BS * NQ * 384];    // [off(256) | attn(128)]
__device__ __align__(16) float g_samp[BS * NQ * EMBED];   // sampled output
__device__ __align__(16) float g_wq[256 * 384];           // tf32-rounded concat(W_off,W_attn)
__device__ __align__(16) float g_wv[256 * 256];           // tf32-rounded W_val
__device__ __align__(16) float g_wo[256 * 256];           // tf32-rounded W_out
__device__ __align__(16) float g_bq[384];                 // concat(b_off, b_attn)

__device__ __forceinline__ uint32_t tf32r(float f) {
    uint32_t r;
    asm("cvt.rna.tf32.f32 %0, %1;" : "=r"(r) : "f"(f));
    return r;
}
__device__ __forceinline__ float tf32f(float f) { return __uint_as_float(tf32r(f)); }

__device__ __forceinline__ uint32_t smem_u32(const void* p) {
    uint32_t a;
    asm("{ .reg .u64 t; cvta.to.shared.u64 t, %1; cvt.u32.u64 %0, t; }" : "=r"(a) : "l"(p));
    return a;
}
__device__ __forceinline__ void cpasync16(uint32_t saddr, const void* g) {
    asm volatile("cp.async.cg.shared.global [%0], [%1], 16;" :: "r"(saddr), "l"(g));
}
__device__ __forceinline__ void cp_commit() {
    asm volatile("cp.async.commit_group;");
}
template <int N> __device__ __forceinline__ void cp_wait() {
    asm volatile("cp.async.wait_group %0;" :: "n"(N));
}

// ---------------------------------------------------------------------------
// Weight pre-conversion (run once per launch; ~1MB of work)
// ---------------------------------------------------------------------------
__global__ void preconv(const float* __restrict__ W_off, const float* __restrict__ W_attn,
                        const float* __restrict__ b_off, const float* __restrict__ b_attn,
                        const float* __restrict__ W_val, const float* __restrict__ W_out)
{
    int i = blockIdx.x * 256 + threadIdx.x;
    if (i < 256 * 384) {
        int k = i / 384, j = i % 384;
        g_wq[i] = tf32f(j < 256 ? W_off[k * 256 + j] : W_attn[k * 128 + (j - 256)]);
    }
    if (i < 256 * 256) {
        g_wv[i] = tf32f(W_val[i]);
        g_wo[i] = tf32f(W_out[i]);
    }
    if (i < 384) g_bq[i] = (i < 256) ? b_off[i] : b_attn[i - 256];
}

// ---------------------------------------------------------------------------
// tf32 mma.sync GEMM v2: C[M, gridDim.y*128] = A[M,256] @ B[256,ldB] + bias
// CTA tile 128x128, BK=32, cp.async 3-stage pipeline, 8 warps (2m x 4n),
// warp tile 64x32 (4x4 m16n8k8 fragments). B pre-rounded to tf32 (no cvt).
// ---------------------------------------------------------------------------
#define TBM 128
#define TBN 128
#define TBK 32
#define ASTR 36
#define BSTR 132
#define STAGE_AW (TBM * ASTR)            // 4608 words
#define STAGE_BW (TBK * BSTR)            // 4224 words
#define STAGE_W  (STAGE_AW + STAGE_BW)   // 8832 words
#define NSTAGE 3
#define GSMEM_BYTES (NSTAGE * STAGE_W * 4)   // 105984 B

__global__ void __launch_bounds__(256, 2) gemm_mma2(
    const float* __restrict__ A, const float* __restrict__ B,
    const float* __restrict__ bias, float* __restrict__ C,
    int M, int ldB, int ldC)
{
    extern __shared__ float sm[];
    const int t      = threadIdx.x;
    const int lane   = t & 31;
    const int wid    = t >> 5;
    const int warp_m = wid & 1;          // 0..1 -> 64 rows each
    const int warp_n = wid >> 1;         // 0..3 -> 32 cols each
    const int m0     = blockIdx.x * TBM;
    const int n0     = blockIdx.y * TBN;
    const int lr     = lane >> 2;        // 0..7
    const int lc     = lane & 3;         // 0..3

    const uint32_t sbase = smem_u32(sm);

    // A row indices for the 4 cp.async chunks this thread handles
    int arow[4];
    #pragma unroll
    for (int i = 0; i < 4; ++i) {
        int idx = t + i * 256;
        int rg = m0 + (idx >> 3);
        if (rg >= M) rg = M - 1;
        arow[i] = rg;
    }

    // issue one K-chunk's loads into stage s
    auto issue = [&](int c, int s) {
        const int k0 = c * TBK;
        const uint32_t st = sbase + (uint32_t)(s * STAGE_W) * 4u;
        #pragma unroll
        for (int i = 0; i < 4; ++i) {
            int idx = t + i * 256;
            int r = idx >> 3, f = idx & 7;
            cpasync16(st + (uint32_t)(r * ASTR + f * 4) * 4u,
                      A + (size_t)arow[i] * 256 + k0 + f * 4);
        }
        #pragma unroll
        for (int i = 0; i < 4; ++i) {
            int idx = t + i * 256;
            int k = idx >> 5, n4 = idx & 31;
            cpasync16(st + (uint32_t)(STAGE_AW + k * BSTR + n4 * 4) * 4u,
                      B + (size_t)(k0 + k) * ldB + n0 + n4 * 4);
        }
        cp_commit();
    };

    float acc[4][4][4];
    #pragma unroll
    for (int i = 0; i < 4; i++)
        #pragma unroll
        for (int j = 0; j < 4; j++)
            #pragma unroll
            for (int r = 0; r < 4; r++) acc[i][j][r] = 0.f;

    issue(0, 0);
    issue(1, 1);

    for (int c = 0; c < 8; ++c) {
        if (c < 7) cp_wait<1>(); else cp_wait<0>();
        __syncthreads();
        if (c + 2 < 8) issue(c + 2, (c + 2) % NSTAGE);

        const float* As_ = sm + (c % NSTAGE) * STAGE_W;
        const float* Bs_ = As_ + STAGE_AW;

        #pragma unroll
        for (int ks = 0; ks < TBK; ks += 8) {
            uint32_t a[4][4], b[4][2];
            #pragma unroll
            for (int mt = 0; mt < 4; ++mt) {
                const int base = warp_m * 64 + mt * 16;
                a[mt][0] = tf32r(As_[(base + lr)     * ASTR + ks + lc]);
                a[mt][1] = tf32r(As_[(base + lr + 8) * ASTR + ks + lc]);
                a[mt][2] = tf32r(As_[(base + lr)     * ASTR + ks + lc + 4]);
                a[mt][3] = tf32r(As_[(base + lr + 8) * ASTR + ks + lc + 4]);
            }
            #pragma unroll
            for (int nt = 0; nt < 4; ++nt) {
                const int n = warp_n * 32 + nt * 8 + lr;
                b[nt][0] = __float_as_uint(Bs_[(ks + lc)     * BSTR + n]);
                b[nt][1] = __float_as_uint(Bs_[(ks + lc + 4) * BSTR + n]);
            }
            #pragma unroll
            for (int mt = 0; mt < 4; ++mt)
                #pragma unroll
                for (int nt = 0; nt < 4; ++nt) {
                    asm volatile(
                        "mma.sync.aligned.m16n8k8.row.col.f32.tf32.tf32.f32 "
                        "{%0,%1,%2,%3}, {%4,%5,%6,%7}, {%8,%9}, {%0,%1,%2,%3};"
                        : "+f"(acc[mt][nt][0]), "+f"(acc[mt][nt][1]),
                          "+f"(acc[mt][nt][2]), "+f"(acc[mt][nt][3])
                        : "r"(a[mt][0]), "r"(a[mt][1]), "r"(a[mt][2]), "r"(a[mt][3]),
                          "r"(b[nt][0]), "r"(b[nt][1]));
                }
        }
        __syncthreads();
    }

    // epilogue: add bias, store
    #pragma unroll
    for (int mt = 0; mt < 4; ++mt) {
        const int row = m0 + warp_m * 64 + mt * 16 + lr;
        #pragma unroll
        for (int nt = 0; nt < 4; ++nt) {
            const int col = n0 + warp_n * 32 + nt * 8 + lc * 2;
            const float b0 = bias[col], b1 = bias[col + 1];
            if (row < M)
                *(float2*)(C + (size_t)row * ldC + col) =
                    make_float2(acc[mt][nt][0] + b0, acc[mt][nt][1] + b1);
            if (row + 8 < M)
                *(float2*)(C + (size_t)(row + 8) * ldC + col) =
                    make_float2(acc[mt][nt][2] + b0, acc[mt][nt][3] + b1);
        }
    }
}

// ---------------------------------------------------------------------------
// Fused softmax + bilinear sampling (R4 structure; reads g_qproj).
// ---------------------------------------------------------------------------
__global__ __launch_bounds__(256) void ms_deform_sample(
    const float* __restrict__ refp)   // [bs, nq, NL, 2]
{
    const int warp = (blockIdx.x * blockDim.x + threadIdx.x) >> 5;
    const int lane = threadIdx.x & 31;
    if (warp >= BS * NQ * NH) return;

    const int h  = warp % NH;
    const int bq = warp / NH;
    const int b  = bq / NQ;

    float logit = -1e30f, xv = 0.f, yv = 0.f;
    if (lane < 16) {
        const float* qp = g_qproj + (size_t)bq * 384;
        logit = qp[256 + h * 16 + lane];
        float ox = qp[h * 32 + lane * 2 + 0];
        float oy = qp[h * 32 + lane * 2 + 1];
        int l = lane >> 2;
        float rx = refp[(bq * NL + l) * 2 + 0];
        float ry = refp[(bq * NL + l) * 2 + 1];
        xv = rx * (float)c_W[l] + ox - 0.5f;
        yv = ry * (float)c_H[l] + oy - 0.5f;
    }

    float m = logit;
    #pragma unroll
    for (int o = 16; o >= 1; o >>= 1) m = fmaxf(m, __shfl_xor_sync(0xFFFFFFFFu, m, o));
    float e = (lane < 16) ? __expf(logit - m) : 0.f;
    float s = e;
    #pragma unroll
    for (int o = 16; o >= 1; o >>= 1) s += __shfl_xor_sync(0xFFFFFFFFu, s, o);
    const float wgt = e / s;

    const int g  = lane >> 3;     // point group 0..3
    const int c4 = lane & 7;      // channel quad 0..7
    const float* vb = g_v + (size_t)b * NV * EMBED + h * HD + c4 * 4;

    float4 acc = make_float4(0.f, 0.f, 0.f, 0.f);

    #pragma unroll
    for (int l = 0; l < NL; ++l) {
        const int p = l * 4 + g;
        const float x  = __shfl_sync(0xFFFFFFFFu, xv,  p);
        const float y  = __shfl_sync(0xFFFFFFFFu, yv,  p);
        const float aw = __shfl_sync(0xFFFFFFFFu, wgt, p);
        const int W  = c_W[l];
        const int H  = c_H[l];
        const int st = c_start[l];

        const float x0f = floorf(x), y0f = floorf(y);
        const int   x0  = (int)x0f,  y0  = (int)y0f;
        const int   x1  = x0 + 1,    y1  = y0 + 1;
        const float fx = x - x0f, fy = y - y0f;

        const float vx0 = (x0 >= 0 && x0 < W) ? 1.f : 0.f;
        const float vx1 = (x1 >= 0 && x1 < W) ? 1.f : 0.f;
        const float vy0 = (y0 >= 0 && y0 < H) ? 1.f : 0.f;
        const float vy1 = (y1 >= 0 && y1 < H) ? 1.f : 0.f;

        const int x0c = min(max(x0, 0), W - 1);
        const int x1c = min(max(x1, 0), W - 1);
        const int y0c = min(max(y0, 0), H - 1);
        const int y1c = min(max(y1, 0), H - 1);

        const float w00 = (1.f - fx) * (1.f - fy) * aw * vx0 * vy0;
        const float w10 = fx * (1.f - fy) * aw * vx1 * vy0;
        const float w01 = (1.f - fx) * fy * aw * vx0 * vy1;
        const float w11 = fx * fy * aw * vx1 * vy1;

        const float* pb = vb + (size_t)st * EMBED;
        const float4 v00 = *(const float4*)(pb + (size_t)(y0c * W + x0c) * EMBED);
        const float4 v10 = *(const float4*)(pb + (size_t)(y0c * W + x1c) * EMBED);
        const float4 v01 = *(const float4*)(pb + (size_t)(y1c * W + x0c) * EMBED);
        const float4 v11 = *(const float4*)(pb + (size_t)(y1c * W + x1c) * EMBED);

        acc.x += w00 * v00.x + w10 * v10.x + w01 * v01.x + w11 * v11.x;
        acc.y += w00 * v00.y + w10 * v10.y + w01 * v01.y + w11 * v11.y;
        acc.z += w00 * v00.z + w10 * v10.z + w01 * v01.z + w11 * v11.z;
        acc.w += w00 * v00.w + w10 * v10.w + w01 * v01.w + w11 * v11.w;
    }

    #pragma unroll
    for (int o = 8; o <= 16; o <<= 1) {
        acc.x += __shfl_xor_sync(0xFFFFFFFFu, acc.x, o);
        acc.y += __shfl_xor_sync(0xFFFFFFFFu, acc.y, o);
        acc.z += __shfl_xor_sync(0xFFFFFFFFu, acc.z, o);
        acc.w += __shfl_xor_sync(0xFFFFFFFFu, acc.w, o);
    }
    if (lane < 8)
        *(float4*)(g_samp + (size_t)bq * EMBED + h * HD + lane * 4) = acc;
}

// ---------------------------------------------------------------------------
extern "C" void kernel_launch(void* const* d_in, const int* in_sizes, int n_in,
                              void* d_out, int out_size)
{
    const float* query  = (const float*)d_in[0];
    const float* value  = (const float*)d_in[1];
    const float* refp   = (const float*)d_in[2];
    const float* W_off  = (const float*)d_in[4];
    const float* b_off  = (const float*)d_in[5];
    const float* W_attn = (const float*)d_in[6];
    const float* b_attn = (const float*)d_in[7];
    const float* W_val  = (const float*)d_in[8];
    const float* b_val  = (const float*)d_in[9];
    const float* W_out  = (const float*)d_in[10];
    const float* b_out  = (const float*)d_in[11];
    float* out = (float*)d_out;

    float* gv;   cudaGetSymbolAddress((void**)&gv,   g_v);
    float* gqp;  cudaGetSymbolAddress((void**)&gqp,  g_qproj);
    float* gsm;  cudaGetSymbolAddress((void**)&gsm,  g_samp);
    float* gwq;  cudaGetSymbolAddress((void**)&gwq,  g_wq);
    float* gwv;  cudaGetSymbolAddress((void**)&gwv,  g_wv);
    float* gwo;  cudaGetSymbolAddress((void**)&gwo,  g_wo);
    float* gbq;  cudaGetSymbolAddress((void**)&gbq,  g_bq);

    cudaFuncSetAttribute(gemm_mma2, cudaFuncAttributeMaxDynamicSharedMemorySize, GSMEM_BYTES);

    const int Mv = BS * NV;      // 53176
    const int Mq = BS * NQ;      // 16000

    // 0) pre-round weights to tf32, concat query-side weights/biases
    preconv<<<384, 256>>>(W_off, W_attn, b_off, b_attn, W_val, W_out);
    // 1) value projection [53176,256] @ [256,256]
    gemm_mma2<<<dim3((Mv + TBM - 1) / TBM, 2), 256, GSMEM_BYTES>>>(value, gwv, b_val, gv, Mv, 256, 256);
    // 2) fused offsets+attn projection [16000,256] @ [256,384]
    gemm_mma2<<<dim3(Mq / TBM, 3), 256, GSMEM_BYTES>>>(query, gwq, gbq, gqp, Mq, 384, 384);
    // 3) fused softmax + bilinear sampling
    {
        int warps = BS * NQ * NH;               // 128000
        int blocks = (warps * 32 + 255) / 256;  // 16000
        ms_deform_sample<<<blocks, 256>>>(refp);
    }
    // 4) output projection [16000,256] @ [256,256]
    gemm_mma2<<<dim3(Mq / TBM, 2), 256, GSMEM_BYTES>>>(gsm, gwo, b_out, out, Mq, 256, 256);
}

// round 7
// speedup vs baseline: 4.9533x; 1.2694x over previous
#include <cuda_runtime.h>
#include <cuda_fp16.h>
#include <cstdint>
#include <cstddef>

// Problem constants (fixed by setup_inputs)
#define BS     4
#define NQ     4000
#define EMBED  256
#define NH     8
#define NL     4
#define NP     4
#define HD     32
#define NV     13294   // 100*100 + 50*50 + 25*25 + 13*13

__constant__ int c_H[NL]     = {100, 50, 25, 13};
__constant__ int c_W[NL]     = {100, 50, 25, 13};
__constant__ int c_start[NL] = {0, 10000, 12500, 13125};

// Scratch (device globals: allocation-free per harness rules)
__device__ __align__(16) float  g_v[BS * NV * EMBED];       // projected value (fp32, gathered)
__device__ __align__(16) float  g_qproj[BS * NQ * 384];     // [off(256) | attn(128)]
__device__ __align__(16) __half g_vh[BS * NV * EMBED];      // fp16 value input
__device__ __align__(16) __half g_qh[BS * NQ * EMBED];      // fp16 query input
__device__ __align__(16) __half g_samph[BS * NQ * EMBED];   // fp16 sampled output
__device__ __align__(16) __half g_wqh[256 * 384];           // fp16 concat(W_off, W_attn)
__device__ __align__(16) __half g_wvh[256 * 256];           // fp16 W_val
__device__ __align__(16) __half g_woh[256 * 256];           // fp16 W_out
__device__ __align__(16) float  g_bq[384];                  // concat(b_off, b_attn)

__device__ __forceinline__ uint32_t pack2(float lo, float hi) {
    uint32_t r;
    asm("cvt.rn.f16x2.f32 %0, %1, %2;" : "=r"(r) : "f"(hi), "f"(lo));
    return r;
}
__device__ __forceinline__ uint32_t smem_u32(const void* p) {
    uint32_t a;
    asm("{ .reg .u64 t; cvta.to.shared.u64 t, %1; cvt.u32.u64 %0, t; }" : "=r"(a) : "l"(p));
    return a;
}
__device__ __forceinline__ void cpasync16(uint32_t saddr, const void* g) {
    asm volatile("cp.async.cg.shared.global [%0], [%1], 16;" :: "r"(saddr), "l"(g));
}
__device__ __forceinline__ void cp_commit() { asm volatile("cp.async.commit_group;"); }
template <int N> __device__ __forceinline__ void cp_wait() {
    asm volatile("cp.async.wait_group %0;" :: "n"(N));
}

#define LDSM_X4(r0, r1, r2, r3, addr) \
    asm volatile("ldmatrix.sync.aligned.m8n8.x4.shared.b16 {%0,%1,%2,%3}, [%4];" \
                 : "=r"(r0), "=r"(r1), "=r"(r2), "=r"(r3) : "r"(addr))
#define LDSM_X4T(r0, r1, r2, r3, addr) \
    asm volatile("ldmatrix.sync.aligned.m8n8.x4.trans.shared.b16 {%0,%1,%2,%3}, [%4];" \
                 : "=r"(r0), "=r"(r1), "=r"(r2), "=r"(r3) : "r"(addr))

// ---------------------------------------------------------------------------
// One-pass fp32 -> fp16 conversion of all GEMM inputs (groups of 8 elements).
// ---------------------------------------------------------------------------
#define VAL8 (BS * NV * 256 / 8)      // 1,701,632
#define Q8   (BS * NQ * 256 / 8)      //   512,000
#define WQ8  (256 * 384 / 8)          //    12,288
#define WV8  (256 * 256 / 8)          //     8,192
#define CV_TOTAL (VAL8 + Q8 + WQ8 + WV8 + WV8 + 48)

__global__ __launch_bounds__(256) void convert_all(
    const float* __restrict__ value, const float* __restrict__ query,
    const float* __restrict__ W_off, const float* __restrict__ W_attn,
    const float* __restrict__ b_off, const float* __restrict__ b_attn,
    const float* __restrict__ W_val, const float* __restrict__ W_out)
{
    int g = blockIdx.x * 256 + threadIdx.x;
    if (g >= CV_TOTAL) return;

    const float* src = nullptr;
    __half* dst = nullptr;
    if (g < VAL8) { src = value + g * 8; dst = g_vh + g * 8; }
    else if ((g -= VAL8) < Q8) { src = query + g * 8; dst = g_qh + g * 8; }
    else if ((g -= Q8) < WQ8) {
        int k = g / 48, j = (g % 48) * 8;
        src = (j < 256) ? W_off + k * 256 + j : W_attn + k * 128 + (j - 256);
        dst = g_wqh + k * 384 + j;
    }
    else if ((g -= WQ8) < WV8) { src = W_val + g * 8; dst = g_wvh + g * 8; }
    else if ((g -= WV8) < WV8) { src = W_out + g * 8; dst = g_woh + g * 8; }
    else {   // bias concat, fp32 copy
        g -= WV8;
        const float* s = (g < 32) ? b_off + g * 8 : b_attn + (g - 32) * 8;
        *(float4*)(g_bq + g * 8)     = *(const float4*)s;
        *(float4*)(g_bq + g * 8 + 4) = *(const float4*)(s + 4);
        return;
    }
    float4 a = *(const float4*)src;
    float4 b = *(const float4*)(src + 4);
    uint4 u;
    u.x = pack2(a.x, a.y); u.y = pack2(a.z, a.w);
    u.z = pack2(b.x, b.y); u.w = pack2(b.z, b.w);
    *(uint4*)dst = u;
}

// ---------------------------------------------------------------------------
// fp16 mma.sync GEMM: C[M, 128*gridDim.y] = A[M,256] @ B[256,ldB] + bias
// CTA 128x128, BK=32, cp.async 3-stage, 8 warps (2m x 4n), warp tile 64x32.
// m16n8k16 fragments via ldmatrix. Strides 40/136 halfs: conflict-free LDSM.
// ---------------------------------------------------------------------------
#define TBM 128
#define TBN 128
#define TBK 32
#define ASTRH 40
#define BSTRH 136
#define STAGE_AH (TBM * ASTRH)           // 5120 halfs
#define STAGE_BH (TBK * BSTRH)           // 4352 halfs
#define STAGE_H  (STAGE_AH + STAGE_BH)   // 9472 halfs (18944 B)
#define NSTAGE 3
#define GSMEM_BYTES (NSTAGE * STAGE_H * 2)

__global__ void __launch_bounds__(256, 2) gemm_h(
    const __half* __restrict__ A, const __half* __restrict__ B,
    const float* __restrict__ bias, float* __restrict__ C,
    int M, int ldB, int ldC)
{
    extern __shared__ __half smh[];
    const int t      = threadIdx.x;
    const int lane   = t & 31;
    const int wid    = t >> 5;
    const int warp_m = wid & 1;
    const int warp_n = wid >> 1;
    const int m0     = blockIdx.x * TBM;
    const int n0     = blockIdx.y * TBN;
    const int lr     = lane >> 2;
    const int lc     = lane & 3;

    const uint32_t sbase = smem_u32(smh);

    int arow[2];
    #pragma unroll
    for (int i = 0; i < 2; ++i) {
        int rg = m0 + ((t + i * 256) >> 2);
        if (rg >= M) rg = M - 1;
        arow[i] = rg;
    }

    auto issue = [&](int c, int s) {
        const int k0 = c * TBK;
        const uint32_t st = sbase + (uint32_t)(s * STAGE_H) * 2u;
        #pragma unroll
        for (int i = 0; i < 2; ++i) {     // A: 128 rows x 32 halfs = 512 chunks
            int idx = t + i * 256;
            int r = idx >> 2, f = idx & 3;
            cpasync16(st + (uint32_t)(r * ASTRH + f * 8) * 2u,
                      A + (size_t)arow[i] * 256 + k0 + f * 8);
        }
        #pragma unroll
        for (int i = 0; i < 2; ++i) {     // B: 32 k-rows x 128 halfs = 512 chunks
            int idx = t + i * 256;
            int k = idx >> 4, n8 = idx & 15;
            cpasync16(st + (uint32_t)(STAGE_AH + k * BSTRH + n8 * 8) * 2u,
                      B + (size_t)(k0 + k) * ldB + n0 + n8 * 8);
        }
        cp_commit();
    };

    float acc[4][4][4];
    #pragma unroll
    for (int i = 0; i < 4; i++)
        #pragma unroll
        for (int j = 0; j < 4; j++)
            #pragma unroll
            for (int r = 0; r < 4; r++) acc[i][j][r] = 0.f;

    issue(0, 0);
    issue(1, 1);

    const uint32_t a_lane_off = (uint32_t)((lane & 15) * ASTRH + (lane >> 4) * 8);
    const uint32_t b_lane_k   = (uint32_t)(lane & 15);
    const uint32_t b_lane_n   = (uint32_t)((lane >> 4) * 8);

    for (int c = 0; c < 8; ++c) {
        if (c < 7) cp_wait<1>(); else cp_wait<0>();
        __syncthreads();
        if (c + 2 < 8) issue(c + 2, (c + 2) % NSTAGE);

        const uint32_t stA = sbase + (uint32_t)((c % NSTAGE) * STAGE_H) * 2u;
        const uint32_t stB = stA + STAGE_AH * 2u;

        #pragma unroll
        for (int ks = 0; ks < TBK; ks += 16) {
            uint32_t a[4][4], b[2][4];
            #pragma unroll
            for (int mt = 0; mt < 4; ++mt) {
                uint32_t ad = stA + ((uint32_t)((warp_m * 64 + mt * 16) * ASTRH + ks) + a_lane_off) * 2u;
                LDSM_X4(a[mt][0], a[mt][1], a[mt][2], a[mt][3], ad);
            }
            #pragma unroll
            for (int np = 0; np < 2; ++np) {
                uint32_t bd = stB + (uint32_t)((ks + b_lane_k) * BSTRH + warp_n * 32 + np * 16 + b_lane_n) * 2u;
                LDSM_X4T(b[np][0], b[np][1], b[np][2], b[np][3], bd);
            }
            #pragma unroll
            for (int mt = 0; mt < 4; ++mt)
                #pragma unroll
                for (int nt = 0; nt < 4; ++nt) {
                    uint32_t b0 = b[nt >> 1][(nt & 1) * 2];
                    uint32_t b1 = b[nt >> 1][(nt & 1) * 2 + 1];
                    asm volatile(
                        "mma.sync.aligned.m16n8k16.row.col.f32.f16.f16.f32 "
                        "{%0,%1,%2,%3}, {%4,%5,%6,%7}, {%8,%9}, {%0,%1,%2,%3};"
                        : "+f"(acc[mt][nt][0]), "+f"(acc[mt][nt][1]),
                          "+f"(acc[mt][nt][2]), "+f"(acc[mt][nt][3])
                        : "r"(a[mt][0]), "r"(a[mt][1]), "r"(a[mt][2]), "r"(a[mt][3]),
                          "r"(b0), "r"(b1));
                }
        }
        __syncthreads();
    }

    #pragma unroll
    for (int mt = 0; mt < 4; ++mt) {
        const int row = m0 + warp_m * 64 + mt * 16 + lr;
        #pragma unroll
        for (int nt = 0; nt < 4; ++nt) {
            const int col = n0 + warp_n * 32 + nt * 8 + lc * 2;
            const float b0 = bias[col], b1 = bias[col + 1];
            if (row < M)
                *(float2*)(C + (size_t)row * ldC + col) =
                    make_float2(acc[mt][nt][0] + b0, acc[mt][nt][1] + b1);
            if (row + 8 < M)
                *(float2*)(C + (size_t)(row + 8) * ldC + col) =
                    make_float2(acc[mt][nt][2] + b0, acc[mt][nt][3] + b1);
        }
    }
}

// ---------------------------------------------------------------------------
// Fused softmax + bilinear sampling (R4 structure); fp16 output for out-proj.
// ---------------------------------------------------------------------------
__global__ __launch_bounds__(256) void ms_deform_sample(
    const float* __restrict__ refp)   // [bs, nq, NL, 2]
{
    const int warp = (blockIdx.x * blockDim.x + threadIdx.x) >> 5;
    const int lane = threadIdx.x & 31;
    if (warp >= BS * NQ * NH) return;

    const int h  = warp % NH;
    const int bq = warp / NH;
    const int b  = bq / NQ;

    float logit = -1e30f, xv = 0.f, yv = 0.f;
    if (lane < 16) {
        const float* qp = g_qproj + (size_t)bq * 384;
        logit = qp[256 + h * 16 + lane];
        float ox = qp[h * 32 + lane * 2 + 0];
        float oy = qp[h * 32 + lane * 2 + 1];
        int l = lane >> 2;
        float rx = refp[(bq * NL + l) * 2 + 0];
        float ry = refp[(bq * NL + l) * 2 + 1];
        xv = rx * (float)c_W[l] + ox - 0.5f;
        yv = ry * (float)c_H[l] + oy - 0.5f;
    }

    float m = logit;
    #pragma unroll
    for (int o = 16; o >= 1; o >>= 1) m = fmaxf(m, __shfl_xor_sync(0xFFFFFFFFu, m, o));
    float e = (lane < 16) ? __expf(logit - m) : 0.f;
    float s = e;
    #pragma unroll
    for (int o = 16; o >= 1; o >>= 1) s += __shfl_xor_sync(0xFFFFFFFFu, s, o);
    const float wgt = e / s;

    const int g  = lane >> 3;
    const int c4 = lane & 7;
    const float* vb = g_v + (size_t)b * NV * EMBED + h * HD + c4 * 4;

    float4 acc = make_float4(0.f, 0.f, 0.f, 0.f);

    #pragma unroll
    for (int l = 0; l < NL; ++l) {
        const int p = l * 4 + g;
        const float x  = __shfl_sync(0xFFFFFFFFu, xv,  p);
        const float y  = __shfl_sync(0xFFFFFFFFu, yv,  p);
        const float aw = __shfl_sync(0xFFFFFFFFu, wgt, p);
        const int W  = c_W[l];
        const int H  = c_H[l];
        const int st = c_start[l];

        const float x0f = floorf(x), y0f = floorf(y);
        const int   x0  = (int)x0f,  y0  = (int)y0f;
        const int   x1  = x0 + 1,    y1  = y0 + 1;
        const float fx = x - x0f, fy = y - y0f;

        const float vx0 = (x0 >= 0 && x0 < W) ? 1.f : 0.f;
        const float vx1 = (x1 >= 0 && x1 < W) ? 1.f : 0.f;
        const float vy0 = (y0 >= 0 && y0 < H) ? 1.f : 0.f;
        const float vy1 = (y1 >= 0 && y1 < H) ? 1.f : 0.f;

        const int x0c = min(max(x0, 0), W - 1);
        const int x1c = min(max(x1, 0), W - 1);
        const int y0c = min(max(y0, 0), H - 1);
        const int y1c = min(max(y1, 0), H - 1);

        const float w00 = (1.f - fx) * (1.f - fy) * aw * vx0 * vy0;
        const float w10 = fx * (1.f - fy) * aw * vx1 * vy0;
        const float w01 = (1.f - fx) * fy * aw * vx0 * vy1;
        const float w11 = fx * fy * aw * vx1 * vy1;

        const float* pb = vb + (size_t)st * EMBED;
        const float4 v00 = *(const float4*)(pb + (size_t)(y0c * W + x0c) * EMBED);
        const float4 v10 = *(const float4*)(pb + (size_t)(y0c * W + x1c) * EMBED);
        const float4 v01 = *(const float4*)(pb + (size_t)(y1c * W + x0c) * EMBED);
        const float4 v11 = *(const float4*)(pb + (size_t)(y1c * W + x1c) * EMBED);

        acc.x += w00 * v00.x + w10 * v10.x + w01 * v01.x + w11 * v11.x;
        acc.y += w00 * v00.y + w10 * v10.y + w01 * v01.y + w11 * v11.y;
        acc.z += w00 * v00.z + w10 * v10.z + w01 * v01.z + w11 * v11.z;
        acc.w += w00 * v00.w + w10 * v10.w + w01 * v01.w + w11 * v11.w;
    }

    #pragma unroll
    for (int o = 8; o <= 16; o <<= 1) {
        acc.x += __shfl_xor_sync(0xFFFFFFFFu, acc.x, o);
        acc.y += __shfl_xor_sync(0xFFFFFFFFu, acc.y, o);
        acc.z += __shfl_xor_sync(0xFFFFFFFFu, acc.z, o);
        acc.w += __shfl_xor_sync(0xFFFFFFFFu, acc.w, o);
    }
    if (lane < 8) {
        uint2 u;
        u.x = pack2(acc.x, acc.y);
        u.y = pack2(acc.z, acc.w);
        *(uint2*)(g_samph + (size_t)bq * EMBED + h * HD + lane * 4) = u;
    }
}

// ---------------------------------------------------------------------------
extern "C" void kernel_launch(void* const* d_in, const int* in_sizes, int n_in,
                              void* d_out, int out_size)
{
    const float* query  = (const float*)d_in[0];
    const float* value  = (const float*)d_in[1];
    const float* refp   = (const float*)d_in[2];
    const float* W_off  = (const float*)d_in[4];
    const float* b_off  = (const float*)d_in[5];
    const float* W_attn = (const float*)d_in[6];
    const float* b_attn = (const float*)d_in[7];
    const float* W_val  = (const float*)d_in[8];
    const float* b_val  = (const float*)d_in[9];
    const float* W_out  = (const float*)d_in[10];
    const float* b_out  = (const float*)d_in[11];
    float* out = (float*)d_out;

    float*  gv;   cudaGetSymbolAddress((void**)&gv,   g_v);
    float*  gqp;  cudaGetSymbolAddress((void**)&gqp,  g_qproj);
    float*  gbq;  cudaGetSymbolAddress((void**)&gbq,  g_bq);
    __half* gvh;  cudaGetSymbolAddress((void**)&gvh,  g_vh);
    __half* gqh;  cudaGetSymbolAddress((void**)&gqh,  g_qh);
    __half* gsh;  cudaGetSymbolAddress((void**)&gsh,  g_samph);
    __half* gwq;  cudaGetSymbolAddress((void**)&gwq,  g_wqh);
    __half* gwv;  cudaGetSymbolAddress((void**)&gwv,  g_wvh);
    __half* gwo;  cudaGetSymbolAddress((void**)&gwo,  g_woh);

    cudaFuncSetAttribute(gemm_h, cudaFuncAttributeMaxDynamicSharedMemorySize, GSMEM_BYTES);

    const int Mv = BS * NV;      // 53176
    const int Mq = BS * NQ;      // 16000

    // 0) convert all GEMM inputs to fp16 (one pass)
    convert_all<<<(CV_TOTAL + 255) / 256, 256>>>(value, query, W_off, W_attn,
                                                 b_off, b_attn, W_val, W_out);
    // 1) value projection [53176,256] @ [256,256] -> fp32 g_v
    gemm_h<<<dim3((Mv + TBM - 1) / TBM, 2), 256, GSMEM_BYTES>>>(gvh, gwv, b_val, gv, Mv, 256, 256);
    // 2) fused offsets+attn projection [16000,256] @ [256,384] -> fp32 g_qproj
    gemm_h<<<dim3(Mq / TBM, 3), 256, GSMEM_BYTES>>>(gqh, gwq, gbq, gqp, Mq, 384, 384);
    // 3) fused softmax + bilinear sampling -> fp16 g_samph
    {
        int warps = BS * NQ * NH;               // 128000
        int blocks = (warps * 32 + 255) / 256;  // 16000
        ms_deform_sample<<<blocks, 256>>>(refp);
    }
    // 4) output projection [16000,256] @ [256,256] -> fp32 out
    gemm_h<<<dim3(Mq / TBM, 2), 256, GSMEM_BYTES>>>(gsh, gwo, b_out, out, Mq, 256, 256);
}

// round 8
// speedup vs baseline: 5.5317x; 1.1168x over previous
#include <cuda_runtime.h>
#include <cuda_fp16.h>
#include <cstdint>
#include <cstddef>

// Problem constants (fixed by setup_inputs)
#define BS     4
#define NQ     4000
#define EMBED  256
#define NH     8
#define NL     4
#define NP     4
#define HD     32
#define NV     13294   // 100*100 + 50*50 + 25*25 + 13*13

__constant__ int c_H[NL]     = {100, 50, 25, 13};
__constant__ int c_W[NL]     = {100, 50, 25, 13};
__constant__ int c_start[NL] = {0, 10000, 12500, 13125};

// Scratch (device globals: allocation-free per harness rules)
__device__ __align__(16) float  g_v[BS * NV * EMBED];       // projected value (fp32)
__device__ __align__(16) float  g_qproj[BS * NQ * 384];     // [off(256) | attn(128)]
__device__ __align__(16) __half g_vh[BS * NV * EMBED];      // fp16 value input
__device__ __align__(16) __half g_qh[BS * NQ * EMBED];      // fp16 query input
__device__ __align__(16) __half g_samph[BS * NQ * EMBED];   // fp16 sampled output
__device__ __align__(16) __half g_wqh[256 * 384];           // fp16 concat(W_off, W_attn)
__device__ __align__(16) __half g_wvh[256 * 256];           // fp16 W_val
__device__ __align__(16) __half g_woh[256 * 256];           // fp16 W_out
__device__ __align__(16) float  g_bq[384];                  // concat(b_off, b_attn)

__device__ __forceinline__ uint32_t pack2(float lo, float hi) {
    uint32_t r;
    asm("cvt.rn.f16x2.f32 %0, %1, %2;" : "=r"(r) : "f"(hi), "f"(lo));
    return r;
}
__device__ __forceinline__ uint32_t smem_u32(const void* p) {
    uint32_t a;
    asm("{ .reg .u64 t; cvta.to.shared.u64 t, %1; cvt.u32.u64 %0, t; }" : "=r"(a) : "l"(p));
    return a;
}
__device__ __forceinline__ void cpasync16(uint32_t saddr, const void* g) {
    asm volatile("cp.async.cg.shared.global [%0], [%1], 16;" :: "r"(saddr), "l"(g));
}
__device__ __forceinline__ void cp_commit() { asm volatile("cp.async.commit_group;"); }
template <int N> __device__ __forceinline__ void cp_wait() {
    asm volatile("cp.async.wait_group %0;" :: "n"(N));
}

#define LDSM_X4(r0, r1, r2, r3, addr) \
    asm volatile("ldmatrix.sync.aligned.m8n8.x4.shared.b16 {%0,%1,%2,%3}, [%4];" \
                 : "=r"(r0), "=r"(r1), "=r"(r2), "=r"(r3) : "r"(addr))
#define LDSM_X4T(r0, r1, r2, r3, addr) \
    asm volatile("ldmatrix.sync.aligned.m8n8.x4.trans.shared.b16 {%0,%1,%2,%3}, [%4];" \
                 : "=r"(r0), "=r"(r1), "=r"(r2), "=r"(r3) : "r"(addr))

// ---------------------------------------------------------------------------
// One-pass fp32 -> fp16 conversion of all GEMM inputs (groups of 8 elements).
// ---------------------------------------------------------------------------
#define VAL8 (BS * NV * 256 / 8)
#define Q8   (BS * NQ * 256 / 8)
#define WQ8  (256 * 384 / 8)
#define WV8  (256 * 256 / 8)
#define CV_TOTAL (VAL8 + Q8 + WQ8 + WV8 + WV8 + 48)

__global__ __launch_bounds__(256) void convert_all(
    const float* __restrict__ value, const float* __restrict__ query,
    const float* __restrict__ W_off, const float* __restrict__ W_attn,
    const float* __restrict__ b_off, const float* __restrict__ b_attn,
    const float* __restrict__ W_val, const float* __restrict__ W_out)
{
    int g = blockIdx.x * 256 + threadIdx.x;
    if (g >= CV_TOTAL) return;

    const float* src = nullptr;
    __half* dst = nullptr;
    if (g < VAL8) { src = value + g * 8; dst = g_vh + g * 8; }
    else if ((g -= VAL8) < Q8) { src = query + g * 8; dst = g_qh + g * 8; }
    else if ((g -= Q8) < WQ8) {
        int k = g / 48, j = (g % 48) * 8;
        src = (j < 256) ? W_off + k * 256 + j : W_attn + k * 128 + (j - 256);
        dst = g_wqh + k * 384 + j;
    }
    else if ((g -= WQ8) < WV8) { src = W_val + g * 8; dst = g_wvh + g * 8; }
    else if ((g -= WV8) < WV8) { src = W_out + g * 8; dst = g_woh + g * 8; }
    else {
        g -= WV8;
        const float* s = (g < 32) ? b_off + g * 8 : b_attn + (g - 32) * 8;
        *(float4*)(g_bq + g * 8)     = *(const float4*)s;
        *(float4*)(g_bq + g * 8 + 4) = *(const float4*)(s + 4);
        return;
    }
    float4 a = *(const float4*)src;
    float4 b = *(const float4*)(src + 4);
    uint4 u;
    u.x = pack2(a.x, a.y); u.y = pack2(a.z, a.w);
    u.z = pack2(b.x, b.y); u.w = pack2(b.z, b.w);
    *(uint4*)dst = u;
}

// ---------------------------------------------------------------------------
// fp16 mma.sync GEMM (unchanged from R7).
// ---------------------------------------------------------------------------
#define TBM 128
#define TBN 128
#define TBK 32
#define ASTRH 40
#define BSTRH 136
#define STAGE_AH (TBM * ASTRH)
#define STAGE_BH (TBK * BSTRH)
#define STAGE_H  (STAGE_AH + STAGE_BH)
#define NSTAGE 3
#define GSMEM_BYTES (NSTAGE * STAGE_H * 2)

__global__ void __launch_bounds__(256, 2) gemm_h(
    const __half* __restrict__ A, const __half* __restrict__ B,
    const float* __restrict__ bias, float* __restrict__ C,
    int M, int ldB, int ldC)
{
    extern __shared__ __half smh[];
    const int t      = threadIdx.x;
    const int lane   = t & 31;
    const int wid    = t >> 5;
    const int warp_m = wid & 1;
    const int warp_n = wid >> 1;
    const int m0     = blockIdx.x * TBM;
    const int n0     = blockIdx.y * TBN;
    const int lr     = lane >> 2;
    const int lc     = lane & 3;

    const uint32_t sbase = smem_u32(smh);

    int arow[2];
    #pragma unroll
    for (int i = 0; i < 2; ++i) {
        int rg = m0 + ((t + i * 256) >> 2);
        if (rg >= M) rg = M - 1;
        arow[i] = rg;
    }

    auto issue = [&](int c, int s) {
        const int k0 = c * TBK;
        const uint32_t st = sbase + (uint32_t)(s * STAGE_H) * 2u;
        #pragma unroll
        for (int i = 0; i < 2; ++i) {
            int idx = t + i * 256;
            int r = idx >> 2, f = idx & 3;
            cpasync16(st + (uint32_t)(r * ASTRH + f * 8) * 2u,
                      A + (size_t)arow[i] * 256 + k0 + f * 8);
        }
        #pragma unroll
        for (int i = 0; i < 2; ++i) {
            int idx = t + i * 256;
            int k = idx >> 4, n8 = idx & 15;
            cpasync16(st + (uint32_t)(STAGE_AH + k * BSTRH + n8 * 8) * 2u,
                      B + (size_t)(k0 + k) * ldB + n0 + n8 * 8);
        }
        cp_commit();
    };

    float acc[4][4][4];
    #pragma unroll
    for (int i = 0; i < 4; i++)
        #pragma unroll
        for (int j = 0; j < 4; j++)
            #pragma unroll
            for (int r = 0; r < 4; r++) acc[i][j][r] = 0.f;

    issue(0, 0);
    issue(1, 1);

    const uint32_t a_lane_off = (uint32_t)((lane & 15) * ASTRH + (lane >> 4) * 8);
    const uint32_t b_lane_k   = (uint32_t)(lane & 15);
    const uint32_t b_lane_n   = (uint32_t)((lane >> 4) * 8);

    for (int c = 0; c < 8; ++c) {
        if (c < 7) cp_wait<1>(); else cp_wait<0>();
        __syncthreads();
        if (c + 2 < 8) issue(c + 2, (c + 2) % NSTAGE);

        const uint32_t stA = sbase + (uint32_t)((c % NSTAGE) * STAGE_H) * 2u;
        const uint32_t stB = stA + STAGE_AH * 2u;

        #pragma unroll
        for (int ks = 0; ks < TBK; ks += 16) {
            uint32_t a[4][4], b[2][4];
            #pragma unroll
            for (int mt = 0; mt < 4; ++mt) {
                uint32_t ad = stA + ((uint32_t)((warp_m * 64 + mt * 16) * ASTRH + ks) + a_lane_off) * 2u;
                LDSM_X4(a[mt][0], a[mt][1], a[mt][2], a[mt][3], ad);
            }
            #pragma unroll
            for (int np = 0; np < 2; ++np) {
                uint32_t bd = stB + (uint32_t)((ks + b_lane_k) * BSTRH + warp_n * 32 + np * 16 + b_lane_n) * 2u;
                LDSM_X4T(b[np][0], b[np][1], b[np][2], b[np][3], bd);
            }
            #pragma unroll
            for (int mt = 0; mt < 4; ++mt)
                #pragma unroll
                for (int nt = 0; nt < 4; ++nt) {
                    uint32_t b0 = b[nt >> 1][(nt & 1) * 2];
                    uint32_t b1 = b[nt >> 1][(nt & 1) * 2 + 1];
                    asm volatile(
                        "mma.sync.aligned.m16n8k16.row.col.f32.f16.f16.f32 "
                        "{%0,%1,%2,%3}, {%4,%5,%6,%7}, {%8,%9}, {%0,%1,%2,%3};"
                        : "+f"(acc[mt][nt][0]), "+f"(acc[mt][nt][1]),
                          "+f"(acc[mt][nt][2]), "+f"(acc[mt][nt][3])
                        : "r"(a[mt][0]), "r"(a[mt][1]), "r"(a[mt][2]), "r"(a[mt][3]),
                          "r"(b0), "r"(b1));
                }
        }
        __syncthreads();
    }

    #pragma unroll
    for (int mt = 0; mt < 4; ++mt) {
        const int row = m0 + warp_m * 64 + mt * 16 + lr;
        #pragma unroll
        for (int nt = 0; nt < 4; ++nt) {
            const int col = n0 + warp_n * 32 + nt * 8 + lc * 2;
            const float b0 = bias[col], b1 = bias[col + 1];
            if (row < M)
                *(float2*)(C + (size_t)row * ldC + col) =
                    make_float2(acc[mt][nt][0] + b0, acc[mt][nt][1] + b1);
            if (row + 8 < M)
                *(float2*)(C + (size_t)(row + 8) * ldC + col) =
                    make_float2(acc[mt][nt][2] + b0, acc[mt][nt][3] + b1);
        }
    }
}

// ---------------------------------------------------------------------------
// Fused softmax + bilinear sampling v3.
// Phase 1: lanes 0..15 compute per-point weights (x attention, x validity)
//          and absolute cell offsets; store 32B/point to SMEM.
// Phase 2: lane group g (8 lanes) loads point record with 2x LDS.128
//          (broadcast in-group, conflict-free across groups), gathers 4
//          corner float4s, 16 FFMA. Per-level scalar math eliminated.
// ---------------------------------------------------------------------------
__global__ __launch_bounds__(256) void ms_deform_sample(
    const float* __restrict__ refp)   // [bs, nq, NL, 2]
{
    __shared__ float sd[8][16][8];    // [warp][point][w00,w10,w01,w11, o00,o10,o01,o11]

    const int wwid = threadIdx.x >> 5;
    const int warp = (blockIdx.x * blockDim.x + threadIdx.x) >> 5;
    const int lane = threadIdx.x & 31;
    if (warp >= BS * NQ * NH) return;

    const int h  = warp % NH;
    const int bq = warp / NH;
    const int b  = bq / NQ;

    float logit = -1e30f, xv = 0.f, yv = 0.f;
    int   Wl = 0, Hl = 0, stl = 0;
    if (lane < 16) {
        const float* qp = g_qproj + (size_t)bq * 384;
        logit = qp[256 + h * 16 + lane];
        float ox = qp[h * 32 + lane * 2 + 0];
        float oy = qp[h * 32 + lane * 2 + 1];
        int l = lane >> 2;
        Wl = c_W[l]; Hl = c_H[l]; stl = c_start[l];
        float rx = refp[(bq * NL + l) * 2 + 0];
        float ry = refp[(bq * NL + l) * 2 + 1];
        xv = rx * (float)Wl + ox - 0.5f;
        yv = ry * (float)Hl + oy - 0.5f;
    }

    // softmax over the 16 points (full-warp butterfly; lanes>=16 neutral)
    float m = logit;
    #pragma unroll
    for (int o = 16; o >= 1; o >>= 1) m = fmaxf(m, __shfl_xor_sync(0xFFFFFFFFu, m, o));
    float e = (lane < 16) ? __expf(logit - m) : 0.f;
    float s = e;
    #pragma unroll
    for (int o = 16; o >= 1; o >>= 1) s += __shfl_xor_sync(0xFFFFFFFFu, s, o);

    if (lane < 16) {
        const float aw = e / s;
        const float x0f = floorf(xv), y0f = floorf(yv);
        const int   x0  = (int)x0f,   y0  = (int)y0f;
        const int   x1  = x0 + 1,     y1  = y0 + 1;
        const float fx = xv - x0f, fy = yv - y0f;

        const float vx0 = (x0 >= 0 && x0 < Wl) ? 1.f : 0.f;
        const float vx1 = (x1 >= 0 && x1 < Wl) ? 1.f : 0.f;
        const float vy0 = (y0 >= 0 && y0 < Hl) ? 1.f : 0.f;
        const float vy1 = (y1 >= 0 && y1 < Hl) ? 1.f : 0.f;

        const int x0c = min(max(x0, 0), Wl - 1);
        const int x1c = min(max(x1, 0), Wl - 1);
        const int y0c = min(max(y0, 0), Hl - 1);
        const int y1c = min(max(y1, 0), Hl - 1);

        float4 w;
        w.x = (1.f - fx) * (1.f - fy) * aw * vx0 * vy0;
        w.y = fx * (1.f - fy) * aw * vx1 * vy0;
        w.z = (1.f - fx) * fy * aw * vx0 * vy1;
        w.w = fx * fy * aw * vx1 * vy1;

        int4 o;
        o.x = (stl + y0c * Wl + x0c) * EMBED;
        o.y = (stl + y0c * Wl + x1c) * EMBED;
        o.z = (stl + y1c * Wl + x0c) * EMBED;
        o.w = (stl + y1c * Wl + x1c) * EMBED;

        *(float4*)&sd[wwid][lane][0] = w;
        *(int4*)  &sd[wwid][lane][4] = o;
    }
    __syncwarp();

    const int g  = lane >> 3;      // point group 0..3
    const int c4 = lane & 7;       // channel quad 0..7
    const float* vb = g_v + (size_t)b * NV * EMBED + h * HD + c4 * 4;

    float4 acc = make_float4(0.f, 0.f, 0.f, 0.f);

    #pragma unroll
    for (int l = 0; l < NL; ++l) {
        const int p = l * 4 + g;
        const float4 w = *(const float4*)&sd[wwid][p][0];
        const int4   o = *(const int4*)  &sd[wwid][p][4];

        const float4 v00 = *(const float4*)(vb + o.x);
        const float4 v10 = *(const float4*)(vb + o.y);
        const float4 v01 = *(const float4*)(vb + o.z);
        const float4 v11 = *(const float4*)(vb + o.w);

        acc.x += w.x * v00.x + w.y * v10.x + w.z * v01.x + w.w * v11.x;
        acc.y += w.x * v00.y + w.y * v10.y + w.z * v01.y + w.w * v11.y;
        acc.z += w.x * v00.z + w.y * v10.z + w.z * v01.z + w.w * v11.z;
        acc.w += w.x * v00.w + w.y * v10.w + w.z * v01.w + w.w * v11.w;
    }

    #pragma unroll
    for (int o = 8; o <= 16; o <<= 1) {
        acc.x += __shfl_xor_sync(0xFFFFFFFFu, acc.x, o);
        acc.y += __shfl_xor_sync(0xFFFFFFFFu, acc.y, o);
        acc.z += __shfl_xor_sync(0xFFFFFFFFu, acc.z, o);
        acc.w += __shfl_xor_sync(0xFFFFFFFFu, acc.w, o);
    }
    if (lane < 8) {
        uint2 u;
        u.x = pack2(acc.x, acc.y);
        u.y = pack2(acc.z, acc.w);
        *(uint2*)(g_samph + (size_t)bq * EMBED + h * HD + lane * 4) = u;
    }
}

// ---------------------------------------------------------------------------
extern "C" void kernel_launch(void* const* d_in, const int* in_sizes, int n_in,
                              void* d_out, int out_size)
{
    const float* query  = (const float*)d_in[0];
    const float* value  = (const float*)d_in[1];
    const float* refp   = (const float*)d_in[2];
    const float* W_off  = (const float*)d_in[4];
    const float* b_off  = (const float*)d_in[5];
    const float* W_attn = (const float*)d_in[6];
    const float* b_attn = (const float*)d_in[7];
    const float* W_val  = (const float*)d_in[8];
    const float* b_val  = (const float*)d_in[9];
    const float* W_out  = (const float*)d_in[10];
    const float* b_out  = (const float*)d_in[11];
    float* out = (float*)d_out;

    float*  gv;   cudaGetSymbolAddress((void**)&gv,   g_v);
    float*  gqp;  cudaGetSymbolAddress((void**)&gqp,  g_qproj);
    float*  gbq;  cudaGetSymbolAddress((void**)&gbq,  g_bq);
    __half* gvh;  cudaGetSymbolAddress((void**)&gvh,  g_vh);
    __half* gqh;  cudaGetSymbolAddress((void**)&gqh,  g_qh);
    __half* gsh;  cudaGetSymbolAddress((void**)&gsh,  g_samph);
    __half* gwq;  cudaGetSymbolAddress((void**)&gwq,  g_wqh);
    __half* gwv;  cudaGetSymbolAddress((void**)&gwv,  g_wvh);
    __half* gwo;  cudaGetSymbolAddress((void**)&gwo,  g_woh);

    cudaFuncSetAttribute(gemm_h, cudaFuncAttributeMaxDynamicSharedMemorySize, GSMEM_BYTES);

    const int Mv = BS * NV;      // 53176
    const int Mq = BS * NQ;      // 16000

    convert_all<<<(CV_TOTAL + 255) / 256, 256>>>(value, query, W_off, W_attn,
                                                 b_off, b_attn, W_val, W_out);
    gemm_h<<<dim3((Mv + TBM - 1) / TBM, 2), 256, GSMEM_BYTES>>>(gvh, gwv, b_val, gv, Mv, 256, 256);
    gemm_h<<<dim3(Mq / TBM, 3), 256, GSMEM_BYTES>>>(gqh, gwq, gbq, gqp, Mq, 384, 384);
    {
        int warps = BS * NQ * NH;               // 128000
        int blocks = (warps * 32 + 255) / 256;  // 16000
        ms_deform_sample<<<blocks, 256>>>(refp);
    }
    gemm_h<<<dim3(Mq / TBM, 2), 256, GSMEM_BYTES>>>(gsh, gwo, b_out, out, Mq, 256, 256);
}

// round 9
// speedup vs baseline: 6.1361x; 1.1092x over previous
#include <cuda_runtime.h>
#include <cuda_fp16.h>
#include <cstdint>
#include <cstddef>

// Problem constants (fixed by setup_inputs)
#define BS     4
#define NQ     4000
#define EMBED  256
#define NH     8
#define NL     4
#define NP     4
#define HD     32
#define NV     13294   // 100*100 + 50*50 + 25*25 + 13*13

__constant__ int c_H[NL]     = {100, 50, 25, 13};
__constant__ int c_W[NL]     = {100, 50, 25, 13};
__constant__ int c_start[NL] = {0, 10000, 12500, 13125};

// Scratch (device globals: allocation-free per harness rules)
__device__ __align__(16) float  g_qproj[BS * NQ * 384];     // [off(256) | attn(128)]
__device__ __align__(16) __half g_vo[BS * NV * EMBED];      // fp16 projected value
__device__ __align__(16) __half g_vh[BS * NV * EMBED];      // fp16 value input
__device__ __align__(16) __half g_qh[BS * NQ * EMBED];      // fp16 query input
__device__ __align__(16) __half g_samph[BS * NQ * EMBED];   // fp16 sampled output
__device__ __align__(16) __half g_wqh[256 * 384];           // fp16 concat(W_off, W_attn)
__device__ __align__(16) __half g_wvh[256 * 256];           // fp16 W_val
__device__ __align__(16) __half g_woh[256 * 256];           // fp16 W_out
__device__ __align__(16) float  g_bq[384];                  // concat(b_off, b_attn)

__device__ __forceinline__ uint32_t pack2(float lo, float hi) {
    uint32_t r;
    asm("cvt.rn.f16x2.f32 %0, %1, %2;" : "=r"(r) : "f"(hi), "f"(lo));
    return r;
}
__device__ __forceinline__ uint32_t smem_u32(const void* p) {
    uint32_t a;
    asm("{ .reg .u64 t; cvta.to.shared.u64 t, %1; cvt.u32.u64 %0, t; }" : "=r"(a) : "l"(p));
    return a;
}
__device__ __forceinline__ void cpasync16(uint32_t saddr, const void* g) {
    asm volatile("cp.async.cg.shared.global [%0], [%1], 16;" :: "r"(saddr), "l"(g));
}
__device__ __forceinline__ void cp_commit() { asm volatile("cp.async.commit_group;"); }
template <int N> __device__ __forceinline__ void cp_wait() {
    asm volatile("cp.async.wait_group %0;" :: "n"(N));
}

#define LDSM_X4(r0, r1, r2, r3, addr) \
    asm volatile("ldmatrix.sync.aligned.m8n8.x4.shared.b16 {%0,%1,%2,%3}, [%4];" \
                 : "=r"(r0), "=r"(r1), "=r"(r2), "=r"(r3) : "r"(addr))
#define LDSM_X4T(r0, r1, r2, r3, addr) \
    asm volatile("ldmatrix.sync.aligned.m8n8.x4.trans.shared.b16 {%0,%1,%2,%3}, [%4];" \
                 : "=r"(r0), "=r"(r1), "=r"(r2), "=r"(r3) : "r"(addr))

// ---------------------------------------------------------------------------
// One-pass fp32 -> fp16 conversion of all GEMM inputs (groups of 8 elements).
// ---------------------------------------------------------------------------
#define VAL8 (BS * NV * 256 / 8)
#define Q8   (BS * NQ * 256 / 8)
#define WQ8  (256 * 384 / 8)
#define WV8  (256 * 256 / 8)
#define CV_TOTAL (VAL8 + Q8 + WQ8 + WV8 + WV8 + 48)

__global__ __launch_bounds__(256) void convert_all(
    const float* __restrict__ value, const float* __restrict__ query,
    const float* __restrict__ W_off, const float* __restrict__ W_attn,
    const float* __restrict__ b_off, const float* __restrict__ b_attn,
    const float* __restrict__ W_val, const float* __restrict__ W_out)
{
    int g = blockIdx.x * 256 + threadIdx.x;
    if (g >= CV_TOTAL) return;

    const float* src = nullptr;
    __half* dst = nullptr;
    if (g < VAL8) { src = value + g * 8; dst = g_vh + g * 8; }
    else if ((g -= VAL8) < Q8) { src = query + g * 8; dst = g_qh + g * 8; }
    else if ((g -= Q8) < WQ8) {
        int k = g / 48, j = (g % 48) * 8;
        src = (j < 256) ? W_off + k * 256 + j : W_attn + k * 128 + (j - 256);
        dst = g_wqh + k * 384 + j;
    }
    else if ((g -= WQ8) < WV8) { src = W_val + g * 8; dst = g_wvh + g * 8; }
    else if ((g -= WV8) < WV8) { src = W_out + g * 8; dst = g_woh + g * 8; }
    else {
        g -= WV8;
        const float* s = (g < 32) ? b_off + g * 8 : b_attn + (g - 32) * 8;
        *(float4*)(g_bq + g * 8)     = *(const float4*)s;
        *(float4*)(g_bq + g * 8 + 4) = *(const float4*)(s + 4);
        return;
    }
    float4 a = *(const float4*)src;
    float4 b = *(const float4*)(src + 4);
    uint4 u;
    u.x = pack2(a.x, a.y); u.y = pack2(a.z, a.w);
    u.z = pack2(b.x, b.y); u.w = pack2(b.z, b.w);
    *(uint4*)dst = u;
}

// ---------------------------------------------------------------------------
// fp16 mma.sync GEMM; templated output dtype (fp32 or fp16).
// ---------------------------------------------------------------------------
#define TBM 128
#define TBN 128
#define TBK 32
#define ASTRH 40
#define BSTRH 136
#define STAGE_AH (TBM * ASTRH)
#define STAGE_BH (TBK * BSTRH)
#define STAGE_H  (STAGE_AH + STAGE_BH)
#define NSTAGE 3
#define GSMEM_BYTES (NSTAGE * STAGE_H * 2)

template <bool HOUT>
__global__ void __launch_bounds__(256, 2) gemm_h(
    const __half* __restrict__ A, const __half* __restrict__ B,
    const float* __restrict__ bias, void* __restrict__ Cv,
    int M, int ldB, int ldC)
{
    extern __shared__ __half smh[];
    const int t      = threadIdx.x;
    const int lane   = t & 31;
    const int wid    = t >> 5;
    const int warp_m = wid & 1;
    const int warp_n = wid >> 1;
    const int m0     = blockIdx.x * TBM;
    const int n0     = blockIdx.y * TBN;
    const int lr     = lane >> 2;
    const int lc     = lane & 3;

    const uint32_t sbase = smem_u32(smh);

    int arow[2];
    #pragma unroll
    for (int i = 0; i < 2; ++i) {
        int rg = m0 + ((t + i * 256) >> 2);
        if (rg >= M) rg = M - 1;
        arow[i] = rg;
    }

    auto issue = [&](int c, int s) {
        const int k0 = c * TBK;
        const uint32_t st = sbase + (uint32_t)(s * STAGE_H) * 2u;
        #pragma unroll
        for (int i = 0; i < 2; ++i) {
            int idx = t + i * 256;
            int r = idx >> 2, f = idx & 3;
            cpasync16(st + (uint32_t)(r * ASTRH + f * 8) * 2u,
                      A + (size_t)arow[i] * 256 + k0 + f * 8);
        }
        #pragma unroll
        for (int i = 0; i < 2; ++i) {
            int idx = t + i * 256;
            int k = idx >> 4, n8 = idx & 15;
            cpasync16(st + (uint32_t)(STAGE_AH + k * BSTRH + n8 * 8) * 2u,
                      B + (size_t)(k0 + k) * ldB + n0 + n8 * 8);
        }
        cp_commit();
    };

    float acc[4][4][4];
    #pragma unroll
    for (int i = 0; i < 4; i++)
        #pragma unroll
        for (int j = 0; j < 4; j++)
            #pragma unroll
            for (int r = 0; r < 4; r++) acc[i][j][r] = 0.f;

    issue(0, 0);
    issue(1, 1);

    const uint32_t a_lane_off = (uint32_t)((lane & 15) * ASTRH + (lane >> 4) * 8);
    const uint32_t b_lane_k   = (uint32_t)(lane & 15);
    const uint32_t b_lane_n   = (uint32_t)((lane >> 4) * 8);

    for (int c = 0; c < 8; ++c) {
        if (c < 7) cp_wait<1>(); else cp_wait<0>();
        __syncthreads();
        if (c + 2 < 8) issue(c + 2, (c + 2) % NSTAGE);

        const uint32_t stA = sbase + (uint32_t)((c % NSTAGE) * STAGE_H) * 2u;
        const uint32_t stB = stA + STAGE_AH * 2u;

        #pragma unroll
        for (int ks = 0; ks < TBK; ks += 16) {
            uint32_t a[4][4], b[2][4];
            #pragma unroll
            for (int mt = 0; mt < 4; ++mt) {
                uint32_t ad = stA + ((uint32_t)((warp_m * 64 + mt * 16) * ASTRH + ks) + a_lane_off) * 2u;
                LDSM_X4(a[mt][0], a[mt][1], a[mt][2], a[mt][3], ad);
            }
            #pragma unroll
            for (int np = 0; np < 2; ++np) {
                uint32_t bd = stB + (uint32_t)((ks + b_lane_k) * BSTRH + warp_n * 32 + np * 16 + b_lane_n) * 2u;
                LDSM_X4T(b[np][0], b[np][1], b[np][2], b[np][3], bd);
            }
            #pragma unroll
            for (int mt = 0; mt < 4; ++mt)
                #pragma unroll
                for (int nt = 0; nt < 4; ++nt) {
                    uint32_t b0 = b[nt >> 1][(nt & 1) * 2];
                    uint32_t b1 = b[nt >> 1][(nt & 1) * 2 + 1];
                    asm volatile(
                        "mma.sync.aligned.m16n8k16.row.col.f32.f16.f16.f32 "
                        "{%0,%1,%2,%3}, {%4,%5,%6,%7}, {%8,%9}, {%0,%1,%2,%3};"
                        : "+f"(acc[mt][nt][0]), "+f"(acc[mt][nt][1]),
                          "+f"(acc[mt][nt][2]), "+f"(acc[mt][nt][3])
                        : "r"(a[mt][0]), "r"(a[mt][1]), "r"(a[mt][2]), "r"(a[mt][3]),
                          "r"(b0), "r"(b1));
                }
        }
        __syncthreads();
    }

    #pragma unroll
    for (int mt = 0; mt < 4; ++mt) {
        const int row = m0 + warp_m * 64 + mt * 16 + lr;
        #pragma unroll
        for (int nt = 0; nt < 4; ++nt) {
            const int col = n0 + warp_n * 32 + nt * 8 + lc * 2;
            const float b0 = bias[col], b1 = bias[col + 1];
            if (HOUT) {
                __half* C = (__half*)Cv;
                if (row < M)
                    *(uint32_t*)(C + (size_t)row * ldC + col) =
                        pack2(acc[mt][nt][0] + b0, acc[mt][nt][1] + b1);
                if (row + 8 < M)
                    *(uint32_t*)(C + (size_t)(row + 8) * ldC + col) =
                        pack2(acc[mt][nt][2] + b0, acc[mt][nt][3] + b1);
            } else {
                float* C = (float*)Cv;
                if (row < M)
                    *(float2*)(C + (size_t)row * ldC + col) =
                        make_float2(acc[mt][nt][0] + b0, acc[mt][nt][1] + b1);
                if (row + 8 < M)
                    *(float2*)(C + (size_t)(row + 8) * ldC + col) =
                        make_float2(acc[mt][nt][2] + b0, acc[mt][nt][3] + b1);
            }
        }
    }
}

// ---------------------------------------------------------------------------
// Fused softmax + bilinear sampling v4: fp16 value gather (8B/lane/corner).
// Phase 1: lanes 0..15 compute per-point weights & absolute cell offsets
//          into SMEM (two 16B records per point, conflict-free).
// Phase 2: lane group g (8 lanes) processes point l*4+g: 4x LDG.64 corner
//          gathers (32 wavefronts/warp total), unpack to fp32, FFMA.
// ---------------------------------------------------------------------------
__global__ __launch_bounds__(256) void ms_deform_sample(
    const float* __restrict__ refp)   // [bs, nq, NL, 2]
{
    __shared__ float sd[8][16][8];    // [warp][point][w00,w10,w01,w11, o00,o10,o01,o11]

    const int wwid = threadIdx.x >> 5;
    const int warp = (blockIdx.x * blockDim.x + threadIdx.x) >> 5;
    const int lane = threadIdx.x & 31;
    if (warp >= BS * NQ * NH) return;

    const int h  = warp % NH;
    const int bq = warp / NH;
    const int b  = bq / NQ;

    float logit = -1e30f, xv = 0.f, yv = 0.f;
    int   Wl = 0, Hl = 0, stl = 0;
    if (lane < 16) {
        const float* qp = g_qproj + (size_t)bq * 384;
        logit = qp[256 + h * 16 + lane];
        float ox = qp[h * 32 + lane * 2 + 0];
        float oy = qp[h * 32 + lane * 2 + 1];
        int l = lane >> 2;
        Wl = c_W[l]; Hl = c_H[l]; stl = c_start[l];
        float rx = refp[(bq * NL + l) * 2 + 0];
        float ry = refp[(bq * NL + l) * 2 + 1];
        xv = rx * (float)Wl + ox - 0.5f;
        yv = ry * (float)Hl + oy - 0.5f;
    }

    float m = logit;
    #pragma unroll
    for (int o = 16; o >= 1; o >>= 1) m = fmaxf(m, __shfl_xor_sync(0xFFFFFFFFu, m, o));
    float e = (lane < 16) ? __expf(logit - m) : 0.f;
    float s = e;
    #pragma unroll
    for (int o = 16; o >= 1; o >>= 1) s += __shfl_xor_sync(0xFFFFFFFFu, s, o);

    if (lane < 16) {
        const float aw = e / s;
        const float x0f = floorf(xv), y0f = floorf(yv);
        const int   x0  = (int)x0f,   y0  = (int)y0f;
        const int   x1  = x0 + 1,     y1  = y0 + 1;
        const float fx = xv - x0f, fy = yv - y0f;

        const float vx0 = (x0 >= 0 && x0 < Wl) ? 1.f : 0.f;
        const float vx1 = (x1 >= 0 && x1 < Wl) ? 1.f : 0.f;
        const float vy0 = (y0 >= 0 && y0 < Hl) ? 1.f : 0.f;
        const float vy1 = (y1 >= 0 && y1 < Hl) ? 1.f : 0.f;

        const int x0c = min(max(x0, 0), Wl - 1);
        const int x1c = min(max(x1, 0), Wl - 1);
        const int y0c = min(max(y0, 0), Hl - 1);
        const int y1c = min(max(y1, 0), Hl - 1);

        float4 w;
        w.x = (1.f - fx) * (1.f - fy) * aw * vx0 * vy0;
        w.y = fx * (1.f - fy) * aw * vx1 * vy0;
        w.z = (1.f - fx) * fy * aw * vx0 * vy1;
        w.w = fx * fy * aw * vx1 * vy1;

        int4 o;
        o.x = (stl + y0c * Wl + x0c) * EMBED;
        o.y = (stl + y0c * Wl + x1c) * EMBED;
        o.z = (stl + y1c * Wl + x0c) * EMBED;
        o.w = (stl + y1c * Wl + x1c) * EMBED;

        *(float4*)&sd[wwid][lane][0] = w;
        *(int4*)  &sd[wwid][lane][4] = o;
    }
    __syncwarp();

    const int g  = lane >> 3;      // point group 0..3
    const int c4 = lane & 7;       // channel quad 0..7
    const __half* vb = g_vo + (size_t)b * NV * EMBED + h * HD + c4 * 4;

    float4 acc = make_float4(0.f, 0.f, 0.f, 0.f);

    #pragma unroll
    for (int l = 0; l < NL; ++l) {
        const int p = l * 4 + g;
        const float4 w = *(const float4*)&sd[wwid][p][0];
        const int4   o = *(const int4*)  &sd[wwid][p][4];

        const uint2 u00 = *(const uint2*)(vb + o.x);
        const uint2 u10 = *(const uint2*)(vb + o.y);
        const uint2 u01 = *(const uint2*)(vb + o.z);
        const uint2 u11 = *(const uint2*)(vb + o.w);

        float2 a0, a1;
        a0 = __half22float2(*(const __half2*)&u00.x);
        a1 = __half22float2(*(const __half2*)&u00.y);
        acc.x += w.x * a0.x; acc.y += w.x * a0.y;
        acc.z += w.x * a1.x; acc.w += w.x * a1.y;

        a0 = __half22float2(*(const __half2*)&u10.x);
        a1 = __half22float2(*(const __half2*)&u10.y);
        acc.x += w.y * a0.x; acc.y += w.y * a0.y;
        acc.z += w.y * a1.x; acc.w += w.y * a1.y;

        a0 = __half22float2(*(const __half2*)&u01.x);
        a1 = __half22float2(*(const __half2*)&u01.y);
        acc.x += w.z * a0.x; acc.y += w.z * a0.y;
        acc.z += w.z * a1.x; acc.w += w.z * a1.y;

        a0 = __half22float2(*(const __half2*)&u11.x);
        a1 = __half22float2(*(const __half2*)&u11.y);
        acc.x += w.w * a0.x; acc.y += w.w * a0.y;
        acc.z += w.w * a1.x; acc.w += w.w * a1.y;
    }

    #pragma unroll
    for (int o = 8; o <= 16; o <<= 1) {
        acc.x += __shfl_xor_sync(0xFFFFFFFFu, acc.x, o);
        acc.y += __shfl_xor_sync(0xFFFFFFFFu, acc.y, o);
        acc.z += __shfl_xor_sync(0xFFFFFFFFu, acc.z, o);
        acc.w += __shfl_xor_sync(0xFFFFFFFFu, acc.w, o);
    }
    if (lane < 8) {
        uint2 u;
        u.x = pack2(acc.x, acc.y);
        u.y = pack2(acc.z, acc.w);
        *(uint2*)(g_samph + (size_t)bq * EMBED + h * HD + lane * 4) = u;
    }
}

// ---------------------------------------------------------------------------
extern "C" void kernel_launch(void* const* d_in, const int* in_sizes, int n_in,
                              void* d_out, int out_size)
{
    const float* query  = (const float*)d_in[0];
    const float* value  = (const float*)d_in[1];
    const float* refp   = (const float*)d_in[2];
    const float* W_off  = (const float*)d_in[4];
    const float* b_off  = (const float*)d_in[5];
    const float* W_attn = (const float*)d_in[6];
    const float* b_attn = (const float*)d_in[7];
    const float* W_val  = (const float*)d_in[8];
    const float* b_val  = (const float*)d_in[9];
    const float* W_out  = (const float*)d_in[10];
    const float* b_out  = (const float*)d_in[11];
    float* out = (float*)d_out;

    float*  gqp;  cudaGetSymbolAddress((void**)&gqp,  g_qproj);
    float*  gbq;  cudaGetSymbolAddress((void**)&gbq,  g_bq);
    __half* gvo;  cudaGetSymbolAddress((void**)&gvo,  g_vo);
    __half* gvh;  cudaGetSymbolAddress((void**)&gvh,  g_vh);
    __half* gqh;  cudaGetSymbolAddress((void**)&gqh,  g_qh);
    __half* gsh;  cudaGetSymbolAddress((void**)&gsh,  g_samph);
    __half* gwq;  cudaGetSymbolAddress((void**)&gwq,  g_wqh);
    __half* gwv;  cudaGetSymbolAddress((void**)&gwv,  g_wvh);
    __half* gwo;  cudaGetSymbolAddress((void**)&gwo,  g_woh);

    cudaFuncSetAttribute(gemm_h<false>, cudaFuncAttributeMaxDynamicSharedMemorySize, GSMEM_BYTES);
    cudaFuncSetAttribute(gemm_h<true>,  cudaFuncAttributeMaxDynamicSharedMemorySize, GSMEM_BYTES);

    const int Mv = BS * NV;      // 53176
    const int Mq = BS * NQ;      // 16000

    convert_all<<<(CV_TOTAL + 255) / 256, 256>>>(value, query, W_off, W_attn,
                                                 b_off, b_attn, W_val, W_out);
    // 1) value projection -> fp16 g_vo
    gemm_h<true><<<dim3((Mv + TBM - 1) / TBM, 2), 256, GSMEM_BYTES>>>(gvh, gwv, b_val, gvo, Mv, 256, 256);
    // 2) fused offsets+attn projection -> fp32 g_qproj
    gemm_h<false><<<dim3(Mq / TBM, 3), 256, GSMEM_BYTES>>>(gqh, gwq, gbq, gqp, Mq, 384, 384);
    // 3) fused softmax + bilinear sampling -> fp16 g_samph
    {
        int warps = BS * NQ * NH;               // 128000
        int blocks = (warps * 32 + 255) / 256;  // 16000
        ms_deform_sample<<<blocks, 256>>>(refp);
    }
    // 4) output projection -> fp32 out
    gemm_h<false><<<dim3(Mq / TBM, 2), 256, GSMEM_BYTES>>>(gsh, gwo, b_out, out, Mq, 256, 256);
}